// round 5
// baseline (speedup 1.0000x reference)
#include <cuda_runtime.h>
#include <math.h>

// Problem constants
constexpr int B_  = 2;
constexpr int S_  = 2048;
constexpr int D_  = 2048;
constexpr int H_  = 16;
constexpr int HD_ = 128;

// Scratch (device globals: no allocation allowed)
__device__ float g_q  [(size_t)B_ * S_ * D_];   // [B,S,D]  (== [B,S,H,HD])
__device__ float g_k  [(size_t)B_ * S_ * HD_];  // [B,S,HD]
__device__ float g_v  [(size_t)B_ * S_ * HD_];  // [B,S,HD]
__device__ float g_att[(size_t)B_ * S_ * D_];   // [B,S,H,HD] flattened

// ---------------------------------------------------------------------------
// SGEMM: C[M,N] = A[M,K] @ W[K,N] + bias[N]
// BM=BN=128, BK=8, 256 threads, 8x8 microtile (split quadrants for
// conflict-free LDS.128 fragment loads). blockIdx.z selects (W0,b0,C0) vs
// (W1,b1,C1) so K and V projections run in one launch.
// Requires: M % 128 == 0, N % 128 == 0 (or N == 128), K % 8 == 0.
// ---------------------------------------------------------------------------
__global__ __launch_bounds__(256, 2)
void sgemm128(const float* __restrict__ A,
              const float* __restrict__ W0, const float* __restrict__ bias0, float* __restrict__ C0,
              const float* __restrict__ W1, const float* __restrict__ bias1, float* __restrict__ C1,
              int N, int K)
{
    const float* W   = (blockIdx.z == 0) ? W0    : W1;
    const float* bia = (blockIdx.z == 0) ? bias0 : bias1;
    float*       C   = (blockIdx.z == 0) ? C0    : C1;

    __shared__ float As[8][132];   // +4 pad: keeps 16B alignment, kills store conflicts
    __shared__ float Bs[8][128];

    const int tid  = threadIdx.x;
    const int row0 = blockIdx.y * 128;
    const int col0 = blockIdx.x * 128;

    // loader mapping
    const int a_row = tid >> 1;          // 0..127
    const int a_col = (tid & 1) * 4;     // 0 or 4
    const int b_row = tid >> 5;          // 0..7
    const int b_col = (tid & 31) * 4;    // 0..124

    // compute mapping (split quadrants: rows {ty*4+i, 64+ty*4+i}, cols likewise)
    const int ty = tid >> 4;             // 0..15
    const int tx = tid & 15;             // 0..15

    float acc[8][8];
#pragma unroll
    for (int i = 0; i < 8; ++i)
#pragma unroll
        for (int j = 0; j < 8; ++j) acc[i][j] = 0.0f;

    const float* Ap = A + (size_t)(row0 + a_row) * K + a_col;
    const float* Wp = W + (size_t)b_row * N + col0 + b_col;

    for (int k0 = 0; k0 < K; k0 += 8) {
        float4 av = *(const float4*)(Ap + k0);
        float4 bv = *(const float4*)(Wp + (size_t)k0 * N);
        As[a_col + 0][a_row] = av.x;
        As[a_col + 1][a_row] = av.y;
        As[a_col + 2][a_row] = av.z;
        As[a_col + 3][a_row] = av.w;
        *(float4*)&Bs[b_row][b_col] = bv;
        __syncthreads();

#pragma unroll
        for (int k = 0; k < 8; ++k) {
            float4 a0 = *(const float4*)&As[k][ty * 4];
            float4 a1 = *(const float4*)&As[k][64 + ty * 4];
            float4 b0 = *(const float4*)&Bs[k][tx * 4];
            float4 b1 = *(const float4*)&Bs[k][64 + tx * 4];
            float ar[8] = {a0.x, a0.y, a0.z, a0.w, a1.x, a1.y, a1.z, a1.w};
            float br[8] = {b0.x, b0.y, b0.z, b0.w, b1.x, b1.y, b1.z, b1.w};
#pragma unroll
            for (int i = 0; i < 8; ++i)
#pragma unroll
                for (int j = 0; j < 8; ++j)
                    acc[i][j] = fmaf(ar[i], br[j], acc[i][j]);
        }
        __syncthreads();
    }

    float4 bb0 = *(const float4*)&bia[col0 + tx * 4];
    float4 bb1 = *(const float4*)&bia[col0 + 64 + tx * 4];
    const float bb[8] = {bb0.x, bb0.y, bb0.z, bb0.w, bb1.x, bb1.y, bb1.z, bb1.w};

#pragma unroll
    for (int i = 0; i < 8; ++i) {
        int r = row0 + ((i < 4) ? (ty * 4 + i) : (64 + ty * 4 + (i - 4)));
        float4 o0 = make_float4(acc[i][0] + bb[0], acc[i][1] + bb[1],
                                acc[i][2] + bb[2], acc[i][3] + bb[3]);
        float4 o1 = make_float4(acc[i][4] + bb[4], acc[i][5] + bb[5],
                                acc[i][6] + bb[6], acc[i][7] + bb[7]);
        *(float4*)&C[(size_t)r * N + col0 + tx * 4]      = o0;
        *(float4*)&C[(size_t)r * N + col0 + 64 + tx * 4] = o1;
    }
}

// ---------------------------------------------------------------------------
// Flash-attention (fp32, online softmax). One block per (q-tile=64, head, batch).
// 256 threads: ty=tid/16 owns rows ty*4..ty*4+3, tx=tid%16 owns score cols
// tx*4..tx*4+3 and output cols {tx*4.., 64+tx*4..}.
// Q and K stored K-transposed in smem so the QK^T inner loop is
// 2x LDS.128 + 16 FFMA per k.
// ---------------------------------------------------------------------------
constexpr int SMEM_FLASH = (128 * 64 + 128 * 64 + 64 * 132 + 64 * 64) * 4; // 115712 B

__global__ __launch_bounds__(256, 2)
void mqa_flash(const float* __restrict__ mask,
               const float* __restrict__ Q,  const float* __restrict__ Kg,
               const float* __restrict__ Vg, float* __restrict__ O)
{
    extern __shared__ float sm[];
    float* Qts = sm;                 // [128][64]   Qts[k][r]
    float* Kts = Qts + 128 * 64;     // [128][64]   Kts[k][c]
    float* Vs  = Kts + 128 * 64;     // [64][132]   Vs[c][d]  (pad 132)
    float* Ps  = Vs  + 64 * 132;     // [64][64]    Ps[r][c]

    const int tid = threadIdx.x;
    const int ty  = tid >> 4;
    const int tx  = tid & 15;
    const int q0  = blockIdx.x * 64;
    const int h   = blockIdx.y;
    const int b   = blockIdx.z;

    const int lrow = tid & 63;          // tile row handled by this loader thread
    const int lcb  = (tid >> 6) * 32;   // 32-col chunk

    // Load Q tile transposed: Qts[k][r] = Q[b, q0+r, h*HD+k]
    {
        const float* qp = Q + ((size_t)(b * S_ + q0 + lrow)) * D_ + h * HD_ + lcb;
#pragma unroll
        for (int u = 0; u < 8; ++u) {
            float4 v = *(const float4*)(qp + u * 4);
            int c = lcb + u * 4;
            Qts[(c + 0) * 64 + lrow] = v.x;
            Qts[(c + 1) * 64 + lrow] = v.y;
            Qts[(c + 2) * 64 + lrow] = v.z;
            Qts[(c + 3) * 64 + lrow] = v.w;
        }
    }

    float m_i[4], l_i[4], o[4][8];
#pragma unroll
    for (int i = 0; i < 4; ++i) {
        m_i[i] = -3.0e38f;
        l_i[i] = 0.0f;
#pragma unroll
        for (int j = 0; j < 8; ++j) o[i][j] = 0.0f;
    }

    const float scale = 0.08838834764831845f;   // 1/sqrt(128)

    for (int kv0 = 0; kv0 < S_; kv0 += 64) {
        // Load K (transposed) and V tiles
        {
            const float* kp = Kg + ((size_t)(b * S_ + kv0 + lrow)) * HD_ + lcb;
            const float* vp = Vg + ((size_t)(b * S_ + kv0 + lrow)) * HD_ + lcb;
#pragma unroll
            for (int u = 0; u < 8; ++u) {
                int c = lcb + u * 4;
                float4 kv4 = *(const float4*)(kp + u * 4);
                Kts[(c + 0) * 64 + lrow] = kv4.x;
                Kts[(c + 1) * 64 + lrow] = kv4.y;
                Kts[(c + 2) * 64 + lrow] = kv4.z;
                Kts[(c + 3) * 64 + lrow] = kv4.w;
                float4 vv4 = *(const float4*)(vp + u * 4);
                *(float4*)&Vs[lrow * 132 + c] = vv4;
            }
        }
        __syncthreads();   // Q (first iter), K, V visible

        // S tile = Q @ K^T  (rows ty*4+i, cols tx*4+j)
        float s[4][4];
#pragma unroll
        for (int i = 0; i < 4; ++i)
#pragma unroll
            for (int j = 0; j < 4; ++j) s[i][j] = 0.0f;

#pragma unroll 8
        for (int k = 0; k < 128; ++k) {
            float4 a  = *(const float4*)&Qts[k * 64 + ty * 4];
            float4 kb = *(const float4*)&Kts[k * 64 + tx * 4];
            float av[4] = {a.x, a.y, a.z, a.w};
            float kv[4] = {kb.x, kb.y, kb.z, kb.w};
#pragma unroll
            for (int i = 0; i < 4; ++i)
#pragma unroll
                for (int j = 0; j < 4; ++j)
                    s[i][j] = fmaf(av[i], kv[j], s[i][j]);
        }

        // scale + additive mask
#pragma unroll
        for (int i = 0; i < 4; ++i) {
            const float* mp = mask + ((size_t)b * S_ + (q0 + ty * 4 + i)) * S_ + kv0 + tx * 4;
            float4 mk = *(const float4*)mp;
            s[i][0] = fmaf(s[i][0], scale, mk.x);
            s[i][1] = fmaf(s[i][1], scale, mk.y);
            s[i][2] = fmaf(s[i][2], scale, mk.z);
            s[i][3] = fmaf(s[i][3], scale, mk.w);
        }

        // online softmax per row (16 lanes share a row -> shfl width 16)
#pragma unroll
        for (int i = 0; i < 4; ++i) {
            float tm = fmaxf(fmaxf(s[i][0], s[i][1]), fmaxf(s[i][2], s[i][3]));
#pragma unroll
            for (int msk = 8; msk >= 1; msk >>= 1)
                tm = fmaxf(tm, __shfl_xor_sync(0xffffffffu, tm, msk, 16));
            float mn = fmaxf(m_i[i], tm);
            float al = __expf(m_i[i] - mn);
            m_i[i] = mn;

            float rs = 0.0f;
#pragma unroll
            for (int j = 0; j < 4; ++j) {
                s[i][j] = __expf(s[i][j] - mn);
                rs += s[i][j];
            }
#pragma unroll
            for (int msk = 8; msk >= 1; msk >>= 1)
                rs += __shfl_xor_sync(0xffffffffu, rs, msk, 16);
            l_i[i] = l_i[i] * al + rs;

#pragma unroll
            for (int j = 0; j < 8; ++j) o[i][j] *= al;

            *(float4*)&Ps[(ty * 4 + i) * 64 + tx * 4] =
                make_float4(s[i][0], s[i][1], s[i][2], s[i][3]);
        }
        __syncthreads();   // Ps visible; all Kts reads done

        // O += P @ V   (output cols: {tx*4+j, 64+tx*4+j})
#pragma unroll 2
        for (int c4 = 0; c4 < 16; ++c4) {
            float4 p0 = *(const float4*)&Ps[(ty * 4 + 0) * 64 + c4 * 4];
            float4 p1 = *(const float4*)&Ps[(ty * 4 + 1) * 64 + c4 * 4];
            float4 p2 = *(const float4*)&Ps[(ty * 4 + 2) * 64 + c4 * 4];
            float4 p3 = *(const float4*)&Ps[(ty * 4 + 3) * 64 + c4 * 4];
            float pr[4][4] = {{p0.x, p0.y, p0.z, p0.w},
                              {p1.x, p1.y, p1.z, p1.w},
                              {p2.x, p2.y, p2.z, p2.w},
                              {p3.x, p3.y, p3.z, p3.w}};
#pragma unroll
            for (int cc = 0; cc < 4; ++cc) {
                int c = c4 * 4 + cc;
                float4 va = *(const float4*)&Vs[c * 132 + tx * 4];
                float4 vb = *(const float4*)&Vs[c * 132 + 64 + tx * 4];
                float vv[8] = {va.x, va.y, va.z, va.w, vb.x, vb.y, vb.z, vb.w};
#pragma unroll
                for (int i = 0; i < 4; ++i)
#pragma unroll
                    for (int j = 0; j < 8; ++j)
                        o[i][j] = fmaf(pr[i][cc], vv[j], o[i][j]);
            }
        }
        __syncthreads();   // PV done before next tile's K/V load
    }

    // finalize: divide by l, write to g_att[b, q0+r, h, :]
#pragma unroll
    for (int i = 0; i < 4; ++i) {
        float inv = 1.0f / l_i[i];
        size_t base = ((size_t)(b * S_ + q0 + ty * 4 + i)) * D_ + h * HD_;
        float4 o0 = make_float4(o[i][0] * inv, o[i][1] * inv, o[i][2] * inv, o[i][3] * inv);
        float4 o1 = make_float4(o[i][4] * inv, o[i][5] * inv, o[i][6] * inv, o[i][7] * inv);
        *(float4*)&O[base + tx * 4]      = o0;
        *(float4*)&O[base + 64 + tx * 4] = o1;
    }
}

// ---------------------------------------------------------------------------
extern "C" void kernel_launch(void* const* d_in, const int* in_sizes, int n_in,
                              void* d_out, int out_size)
{
    (void)in_sizes; (void)n_in; (void)out_size;
    const float* x    = (const float*)d_in[0];
    const float* mask = (const float*)d_in[1];
    const float* wq_w = (const float*)d_in[2];
    const float* wq_b = (const float*)d_in[3];
    const float* wk_w = (const float*)d_in[4];
    const float* wk_b = (const float*)d_in[5];
    const float* wv_w = (const float*)d_in[6];
    const float* wv_b = (const float*)d_in[7];
    const float* wo_w = (const float*)d_in[8];
    const float* wo_b = (const float*)d_in[9];
    float* out = (float*)d_out;

    float *qb, *kb, *vb, *ab;
    cudaGetSymbolAddress((void**)&qb, g_q);
    cudaGetSymbolAddress((void**)&kb, g_k);
    cudaGetSymbolAddress((void**)&vb, g_v);
    cudaGetSymbolAddress((void**)&ab, g_att);

    cudaFuncSetAttribute(mqa_flash, cudaFuncAttributeMaxDynamicSharedMemorySize, SMEM_FLASH);

    dim3 blk(256);
    // Q = x @ wq + bq           [4096,2048] x [2048,2048]
    sgemm128<<<dim3(16, 32, 1), blk>>>(x, wq_w, wq_b, qb, wq_w, wq_b, qb, D_, D_);
    // K,V = x @ wk/wv + b       [4096,2048] x [2048,128], one launch (z selects)
    sgemm128<<<dim3(1, 32, 2), blk>>>(x, wk_w, wk_b, kb, wv_w, wv_b, vb, HD_, D_);
    // attention
    mqa_flash<<<dim3(S_ / 64, H_, B_), blk, SMEM_FLASH>>>(mask, qb, kb, vb, ab);
    // out = att @ wo + bo
    sgemm128<<<dim3(16, 32, 1), blk>>>(ab, wo_w, wo_b, out, wo_w, wo_b, out, D_, D_);
}

// round 7
// speedup vs baseline: 1.2809x; 1.2809x over previous
#include <cuda_runtime.h>
#include <cuda_bf16.h>
#include <cstdint>
#include <math.h>

// Problem constants
constexpr int B_  = 2;
constexpr int S_  = 2048;
constexpr int D_  = 2048;
constexpr int H_  = 16;
constexpr int HD_ = 128;

// Scratch (device globals: no allocation allowed)
__device__ float g_q  [(size_t)B_ * S_ * D_];   // [B,S,D]  (== [B,S,H,HD])
__device__ float g_k  [(size_t)B_ * S_ * HD_];  // [B,S,HD]
__device__ float g_v  [(size_t)B_ * S_ * HD_];  // [B,S,HD]
__device__ float g_att[(size_t)B_ * S_ * D_];   // [B,S,H,HD] flattened

// ===========================================================================
// PTX helpers — baseline ISA only (mma.sync sm_80+, ldmatrix sm_75+).
// No tcgen05/TMEM: harness ptxas target is sm_103 (no 'a' feature set).
// ===========================================================================
__device__ __forceinline__ uint32_t smem_u32(const void* p) {
    uint32_t a;
    asm("{ .reg .u64 t; cvta.to.shared.u64 t, %1; cvt.u32.u64 %0, t; }"
        : "=r"(a) : "l"(p));
    return a;
}

__device__ __forceinline__ void ldsm_x4(uint32_t* r, uint32_t addr) {
    asm volatile("ldmatrix.sync.aligned.m8n8.x4.shared.b16 {%0,%1,%2,%3}, [%4];"
                 : "=r"(r[0]), "=r"(r[1]), "=r"(r[2]), "=r"(r[3]) : "r"(addr));
}
__device__ __forceinline__ void ldsm_x2_t(uint32_t* r, uint32_t addr) {
    asm volatile("ldmatrix.sync.aligned.m8n8.x2.trans.shared.b16 {%0,%1}, [%2];"
                 : "=r"(r[0]), "=r"(r[1]) : "r"(addr));
}
// D = A(16x16 bf16) * B(16x8 bf16) + D (fp32)
__device__ __forceinline__ void mma16816(float* c, const uint32_t* a, const uint32_t* b) {
    asm volatile(
        "mma.sync.aligned.m16n8k16.row.col.f32.bf16.bf16.f32 "
        "{%0,%1,%2,%3}, {%4,%5,%6,%7}, {%8,%9}, {%0,%1,%2,%3};"
        : "+f"(c[0]), "+f"(c[1]), "+f"(c[2]), "+f"(c[3])
        : "r"(a[0]), "r"(a[1]), "r"(a[2]), "r"(a[3]), "r"(b[0]), "r"(b[1]));
}

// fp32 -> (hi, lo) bf16 split, packed as 2x u32 per float4
__device__ __forceinline__ void split4(float4 v, uint2& hp, uint2& lp) {
    __nv_bfloat16 hx = __float2bfloat16(v.x), hy = __float2bfloat16(v.y);
    __nv_bfloat16 hz = __float2bfloat16(v.z), hw = __float2bfloat16(v.w);
    __nv_bfloat16 lx = __float2bfloat16(v.x - __bfloat162float(hx));
    __nv_bfloat16 ly = __float2bfloat16(v.y - __bfloat162float(hy));
    __nv_bfloat16 lz = __float2bfloat16(v.z - __bfloat162float(hz));
    __nv_bfloat16 lw = __float2bfloat16(v.w - __bfloat162float(hw));
    hp.x = (uint32_t)__bfloat16_as_ushort(hx) | ((uint32_t)__bfloat16_as_ushort(hy) << 16);
    hp.y = (uint32_t)__bfloat16_as_ushort(hz) | ((uint32_t)__bfloat16_as_ushort(hw) << 16);
    lp.x = (uint32_t)__bfloat16_as_ushort(lx) | ((uint32_t)__bfloat16_as_ushort(ly) << 16);
    lp.y = (uint32_t)__bfloat16_as_ushort(lz) | ((uint32_t)__bfloat16_as_ushort(lw) << 16);
}

// ===========================================================================
// HMMA bf16-split GEMM: C[M,N] = A[M,K] @ W[K,N] + bias[N]   (fp32 I/O)
// CTA tile 128x128, K chunk 32. 8 warps in 2(m) x 4(n); warp tile 64x32.
// Split precision: a = hi + lo (bf16); D += Ah*Bh + Ah*Bl + Al*Bh (fp32 acc).
// A smem [128][SA=40] k-contig (ldmatrix.x4, conflict-free @80B stride).
// B smem [32][SB=136] n-contig (ldmatrix.x2.trans, conflict-free @272B stride).
// blockIdx.z selects (W0,b0,C0) vs (W1,b1,C1).
// Requires M%128==0, N%128==0, K%32==0.
// ===========================================================================
constexpr int KC = 32;
constexpr int SA = 40;                     // A smem row stride (elems)
constexpr int SB = 136;                    // B smem row stride (elems)
constexpr int A_TILE = 128 * SA;           // 5120 elems
constexpr int B_TILE = KC * SB;            // 4352 elems
constexpr int STAGE_ELEMS = 2 * A_TILE + 2 * B_TILE;   // Ah,Al,Bh,Bl = 18944
constexpr int SMEM_GEMM = 2 * STAGE_ELEMS * 2;         // 75776 B

__global__ __launch_bounds__(256)
void tc_gemm(const float* __restrict__ A,
             const float* __restrict__ W0, const float* __restrict__ bias0, float* __restrict__ C0,
             const float* __restrict__ W1, const float* __restrict__ bias1, float* __restrict__ C1,
             int N, int K)
{
    const float* W   = (blockIdx.z == 0) ? W0    : W1;
    const float* bia = (blockIdx.z == 0) ? bias0 : bias1;
    float*       C   = (blockIdx.z == 0) ? C0    : C1;

    extern __shared__ unsigned short smu[];
    const int tid  = threadIdx.x;
    const int wid  = tid >> 5;
    const int lane = tid & 31;
    const int row0 = blockIdx.y * 128;
    const int col0 = blockIdx.x * 128;

    const int wm = wid >> 2;               // 0..1  -> rows wm*64
    const int wn = wid & 3;                // 0..3  -> cols wn*32
    const int la = lane & 15;
    const int lb = lane >> 4;

    // ldmatrix byte offsets within a tile (add stage base; add kk step below)
    uint32_t offA[4], offB[4];
#pragma unroll
    for (int mi = 0; mi < 4; ++mi)
        offA[mi] = (uint32_t)(((wm * 64 + mi * 16 + la) * SA + lb * 8) * 2);
#pragma unroll
    for (int ni = 0; ni < 4; ++ni)
        offB[ni] = (uint32_t)((la * SB + wn * 32 + ni * 8) * 2);

    const uint32_t sb = smem_u32(smu);

    // loader index mapping (4 float4 per thread for A and for B)
    // A: idx = u*256+tid: r = idx>>3 (0..127), c4 = idx&7
    // B: idx = u*256+tid: k = idx>>5 (0..31),  n4 = idx&31
    float4 pvA[4], pvB[4];

    auto ldg_chunk = [&](int c) {
        const int kc = c * KC;
#pragma unroll
        for (int u = 0; u < 4; ++u) {
            int idx = u * 256 + tid;
            int r = idx >> 3, c4 = idx & 7;
            pvA[u] = *(const float4*)(A + (size_t)(row0 + r) * K + kc + c4 * 4);
            int k = idx >> 5, n4 = idx & 31;
            pvB[u] = *(const float4*)(W + (size_t)(kc + k) * N + col0 + n4 * 4);
        }
    };
    auto sts_chunk = [&](int stg) {
        unsigned short* Ah = smu + (size_t)stg * STAGE_ELEMS;
        unsigned short* Al = Ah + A_TILE;
        unsigned short* Bh = Al + A_TILE;
        unsigned short* Bl = Bh + B_TILE;
#pragma unroll
        for (int u = 0; u < 4; ++u) {
            int idx = u * 256 + tid;
            uint2 hp, lp;
            int r = idx >> 3, c4 = idx & 7;
            split4(pvA[u], hp, lp);
            *(uint2*)&Ah[r * SA + c4 * 4] = hp;
            *(uint2*)&Al[r * SA + c4 * 4] = lp;
            int k = idx >> 5, n4 = idx & 31;
            split4(pvB[u], hp, lp);
            *(uint2*)&Bh[k * SB + n4 * 4] = hp;
            *(uint2*)&Bl[k * SB + n4 * 4] = lp;
        }
    };

    float acc[4][4][4];
#pragma unroll
    for (int mi = 0; mi < 4; ++mi)
#pragma unroll
        for (int ni = 0; ni < 4; ++ni)
#pragma unroll
            for (int r = 0; r < 4; ++r) acc[mi][ni][r] = 0.0f;

    ldg_chunk(0);
    sts_chunk(0);
    __syncthreads();

    const int NCH = K / KC;
    for (int ci = 0; ci < NCH; ++ci) {
        const int cur = ci & 1;
        const bool more = (ci + 1 < NCH);
        if (more) ldg_chunk(ci + 1);       // LDG in flight while MMAs run

        const uint32_t bAh = sb + (uint32_t)(cur * STAGE_ELEMS) * 2;
        const uint32_t bAl = bAh + A_TILE * 2;
        const uint32_t bBh = bAl + A_TILE * 2;
        const uint32_t bBl = bBh + B_TILE * 2;

#pragma unroll
        for (int kk = 0; kk < 2; ++kk) {
            const uint32_t dA = (uint32_t)(kk * 16 * 2);        // +16 k-elems
            const uint32_t dB = (uint32_t)(kk * 16 * SB * 2);   // +16 k-rows
            uint32_t ah[4][4], al[4][4], bh[4][2], bl[4][2];
#pragma unroll
            for (int mi = 0; mi < 4; ++mi) {
                ldsm_x4(ah[mi], bAh + offA[mi] + dA);
                ldsm_x4(al[mi], bAl + offA[mi] + dA);
            }
#pragma unroll
            for (int ni = 0; ni < 4; ++ni) {
                ldsm_x2_t(bh[ni], bBh + offB[ni] + dB);
                ldsm_x2_t(bl[ni], bBl + offB[ni] + dB);
            }
            // three split passes; each acc reused once per 16 MMAs
#pragma unroll
            for (int mi = 0; mi < 4; ++mi)
#pragma unroll
                for (int ni = 0; ni < 4; ++ni)
                    mma16816(acc[mi][ni], ah[mi], bh[ni]);
#pragma unroll
            for (int mi = 0; mi < 4; ++mi)
#pragma unroll
                for (int ni = 0; ni < 4; ++ni)
                    mma16816(acc[mi][ni], ah[mi], bl[ni]);
#pragma unroll
            for (int mi = 0; mi < 4; ++mi)
#pragma unroll
                for (int ni = 0; ni < 4; ++ni)
                    mma16816(acc[mi][ni], al[mi], bh[ni]);
        }

        if (more) sts_chunk(cur ^ 1);      // fill other stage
        __syncthreads();
    }

    // ---- epilogue: acc + bias -> C ----
    const int g = lane >> 2, t = lane & 3;
#pragma unroll
    for (int mi = 0; mi < 4; ++mi) {
#pragma unroll
        for (int ni = 0; ni < 4; ++ni) {
            int row = row0 + wm * 64 + mi * 16 + g;
            int col = col0 + wn * 32 + ni * 8 + 2 * t;
            float b0v = bia[col], b1v = bia[col + 1];
            *(float2*)&C[(size_t)row * N + col] =
                make_float2(acc[mi][ni][0] + b0v, acc[mi][ni][1] + b1v);
            *(float2*)&C[(size_t)(row + 8) * N + col] =
                make_float2(acc[mi][ni][2] + b0v, acc[mi][ni][3] + b1v);
        }
    }
}

// ---------------------------------------------------------------------------
// Flash-attention (fp32, online softmax) — unchanged from R5 baseline.
// ---------------------------------------------------------------------------
constexpr int SMEM_FLASH = (128 * 64 + 128 * 64 + 64 * 132 + 64 * 64) * 4; // 115712 B

__global__ __launch_bounds__(256, 2)
void mqa_flash(const float* __restrict__ mask,
               const float* __restrict__ Q,  const float* __restrict__ Kg,
               const float* __restrict__ Vg, float* __restrict__ O)
{
    extern __shared__ float smf[];
    float* Qts = smf;                // [128][64]   Qts[k][r]
    float* Kts = Qts + 128 * 64;     // [128][64]   Kts[k][c]
    float* Vs  = Kts + 128 * 64;     // [64][132]   Vs[c][d]  (pad 132)
    float* Ps  = Vs  + 64 * 132;     // [64][64]    Ps[r][c]

    const int tid = threadIdx.x;
    const int ty  = tid >> 4;
    const int tx  = tid & 15;
    const int q0  = blockIdx.x * 64;
    const int h   = blockIdx.y;
    const int b   = blockIdx.z;

    const int lrow = tid & 63;
    const int lcb  = (tid >> 6) * 32;

    {
        const float* qp = Q + ((size_t)(b * S_ + q0 + lrow)) * D_ + h * HD_ + lcb;
#pragma unroll
        for (int u = 0; u < 8; ++u) {
            float4 v = *(const float4*)(qp + u * 4);
            int c = lcb + u * 4;
            Qts[(c + 0) * 64 + lrow] = v.x;
            Qts[(c + 1) * 64 + lrow] = v.y;
            Qts[(c + 2) * 64 + lrow] = v.z;
            Qts[(c + 3) * 64 + lrow] = v.w;
        }
    }

    float m_i[4], l_i[4], o[4][8];
#pragma unroll
    for (int i = 0; i < 4; ++i) {
        m_i[i] = -3.0e38f;
        l_i[i] = 0.0f;
#pragma unroll
        for (int j = 0; j < 8; ++j) o[i][j] = 0.0f;
    }

    const float scale = 0.08838834764831845f;   // 1/sqrt(128)

    for (int kv0 = 0; kv0 < S_; kv0 += 64) {
        {
            const float* kp = Kg + ((size_t)(b * S_ + kv0 + lrow)) * HD_ + lcb;
            const float* vp = Vg + ((size_t)(b * S_ + kv0 + lrow)) * HD_ + lcb;
#pragma unroll
            for (int u = 0; u < 8; ++u) {
                int c = lcb + u * 4;
                float4 kv4 = *(const float4*)(kp + u * 4);
                Kts[(c + 0) * 64 + lrow] = kv4.x;
                Kts[(c + 1) * 64 + lrow] = kv4.y;
                Kts[(c + 2) * 64 + lrow] = kv4.z;
                Kts[(c + 3) * 64 + lrow] = kv4.w;
                float4 vv4 = *(const float4*)(vp + u * 4);
                *(float4*)&Vs[lrow * 132 + c] = vv4;
            }
        }
        __syncthreads();

        float s[4][4];
#pragma unroll
        for (int i = 0; i < 4; ++i)
#pragma unroll
            for (int j = 0; j < 4; ++j) s[i][j] = 0.0f;

#pragma unroll 8
        for (int k = 0; k < 128; ++k) {
            float4 a  = *(const float4*)&Qts[k * 64 + ty * 4];
            float4 kb = *(const float4*)&Kts[k * 64 + tx * 4];
            float av[4] = {a.x, a.y, a.z, a.w};
            float kv[4] = {kb.x, kb.y, kb.z, kb.w};
#pragma unroll
            for (int i = 0; i < 4; ++i)
#pragma unroll
                for (int j = 0; j < 4; ++j)
                    s[i][j] = fmaf(av[i], kv[j], s[i][j]);
        }

#pragma unroll
        for (int i = 0; i < 4; ++i) {
            const float* mp = mask + ((size_t)b * S_ + (q0 + ty * 4 + i)) * S_ + kv0 + tx * 4;
            float4 mk = *(const float4*)mp;
            s[i][0] = fmaf(s[i][0], scale, mk.x);
            s[i][1] = fmaf(s[i][1], scale, mk.y);
            s[i][2] = fmaf(s[i][2], scale, mk.z);
            s[i][3] = fmaf(s[i][3], scale, mk.w);
        }

#pragma unroll
        for (int i = 0; i < 4; ++i) {
            float tm = fmaxf(fmaxf(s[i][0], s[i][1]), fmaxf(s[i][2], s[i][3]));
#pragma unroll
            for (int msk = 8; msk >= 1; msk >>= 1)
                tm = fmaxf(tm, __shfl_xor_sync(0xffffffffu, tm, msk, 16));
            float mn = fmaxf(m_i[i], tm);
            float al = __expf(m_i[i] - mn);
            m_i[i] = mn;

            float rs = 0.0f;
#pragma unroll
            for (int j = 0; j < 4; ++j) {
                s[i][j] = __expf(s[i][j] - mn);
                rs += s[i][j];
            }
#pragma unroll
            for (int msk = 8; msk >= 1; msk >>= 1)
                rs += __shfl_xor_sync(0xffffffffu, rs, msk, 16);
            l_i[i] = l_i[i] * al + rs;

#pragma unroll
            for (int j = 0; j < 8; ++j) o[i][j] *= al;

            *(float4*)&Ps[(ty * 4 + i) * 64 + tx * 4] =
                make_float4(s[i][0], s[i][1], s[i][2], s[i][3]);
        }
        __syncthreads();

#pragma unroll 2
        for (int c4 = 0; c4 < 16; ++c4) {
            float4 p0 = *(const float4*)&Ps[(ty * 4 + 0) * 64 + c4 * 4];
            float4 p1 = *(const float4*)&Ps[(ty * 4 + 1) * 64 + c4 * 4];
            float4 p2 = *(const float4*)&Ps[(ty * 4 + 2) * 64 + c4 * 4];
            float4 p3 = *(const float4*)&Ps[(ty * 4 + 3) * 64 + c4 * 4];
            float pr[4][4] = {{p0.x, p0.y, p0.z, p0.w},
                              {p1.x, p1.y, p1.z, p1.w},
                              {p2.x, p2.y, p2.z, p2.w},
                              {p3.x, p3.y, p3.z, p3.w}};
#pragma unroll
            for (int cc = 0; cc < 4; ++cc) {
                int c = c4 * 4 + cc;
                float4 va = *(const float4*)&Vs[c * 132 + tx * 4];
                float4 vb = *(const float4*)&Vs[c * 132 + 64 + tx * 4];
                float vv[8] = {va.x, va.y, va.z, va.w, vb.x, vb.y, vb.z, vb.w};
#pragma unroll
                for (int i = 0; i < 4; ++i)
#pragma unroll
                    for (int j = 0; j < 8; ++j)
                        o[i][j] = fmaf(pr[i][cc], vv[j], o[i][j]);
            }
        }
        __syncthreads();
    }

#pragma unroll
    for (int i = 0; i < 4; ++i) {
        float inv = 1.0f / l_i[i];
        size_t base = ((size_t)(b * S_ + q0 + ty * 4 + i)) * D_ + h * HD_;
        float4 o0 = make_float4(o[i][0] * inv, o[i][1] * inv, o[i][2] * inv, o[i][3] * inv);
        float4 o1 = make_float4(o[i][4] * inv, o[i][5] * inv, o[i][6] * inv, o[i][7] * inv);
        *(float4*)&O[base + tx * 4]      = o0;
        *(float4*)&O[base + 64 + tx * 4] = o1;
    }
}

// ---------------------------------------------------------------------------
extern "C" void kernel_launch(void* const* d_in, const int* in_sizes, int n_in,
                              void* d_out, int out_size)
{
    (void)in_sizes; (void)n_in; (void)out_size;
    const float* x    = (const float*)d_in[0];
    const float* mask = (const float*)d_in[1];
    const float* wq_w = (const float*)d_in[2];
    const float* wq_b = (const float*)d_in[3];
    const float* wk_w = (const float*)d_in[4];
    const float* wk_b = (const float*)d_in[5];
    const float* wv_w = (const float*)d_in[6];
    const float* wv_b = (const float*)d_in[7];
    const float* wo_w = (const float*)d_in[8];
    const float* wo_b = (const float*)d_in[9];
    float* out = (float*)d_out;

    float *qb, *kb, *vb, *ab;
    cudaGetSymbolAddress((void**)&qb, g_q);
    cudaGetSymbolAddress((void**)&kb, g_k);
    cudaGetSymbolAddress((void**)&vb, g_v);
    cudaGetSymbolAddress((void**)&ab, g_att);

    cudaFuncSetAttribute(tc_gemm,   cudaFuncAttributeMaxDynamicSharedMemorySize, SMEM_GEMM);
    cudaFuncSetAttribute(mqa_flash, cudaFuncAttributeMaxDynamicSharedMemorySize, SMEM_FLASH);

    dim3 blk(256);
    // Q = x @ wq + bq           [4096,2048] x [2048,2048]
    tc_gemm<<<dim3(16, 32, 1), blk, SMEM_GEMM>>>(x, wq_w, wq_b, qb, wq_w, wq_b, qb, D_, D_);
    // K,V = x @ wk/wv + b       [4096,2048] x [2048,128], z selects K vs V
    tc_gemm<<<dim3(1, 32, 2), blk, SMEM_GEMM>>>(x, wk_w, wk_b, kb, wv_w, wv_b, vb, HD_, D_);
    // attention (fp32 flash, unchanged this round)
    mqa_flash<<<dim3(S_ / 64, H_, B_), blk, SMEM_FLASH>>>(mask, qb, kb, vb, ab);
    // out = att @ wo + bo
    tc_gemm<<<dim3(16, 32, 1), blk, SMEM_GEMM>>>(ab, wo_w, wo_b, out, wo_w, wo_b, out, D_, D_);
}

// round 8
// speedup vs baseline: 2.2033x; 1.7201x over previous
#include <cuda_runtime.h>
#include <cuda_bf16.h>
#include <cstdint>
#include <math.h>

// Problem constants
constexpr int B_  = 2;
constexpr int S_  = 2048;
constexpr int D_  = 2048;
constexpr int H_  = 16;
constexpr int HD_ = 128;

// Scratch (device globals: no allocation allowed)
__device__ float g_q  [(size_t)B_ * S_ * D_];   // [B,S,D]  (== [B,S,H,HD])
__device__ float g_k  [(size_t)B_ * S_ * HD_];  // [B,S,HD]
__device__ float g_v  [(size_t)B_ * S_ * HD_];  // [B,S,HD]
__device__ float g_att[(size_t)B_ * S_ * D_];   // [B,S,H,HD] flattened

// ===========================================================================
// PTX helpers — baseline ISA only (mma.sync sm_80+, ldmatrix sm_75+).
// ===========================================================================
__device__ __forceinline__ uint32_t smem_u32(const void* p) {
    uint32_t a;
    asm("{ .reg .u64 t; cvta.to.shared.u64 t, %1; cvt.u32.u64 %0, t; }"
        : "=r"(a) : "l"(p));
    return a;
}

__device__ __forceinline__ void ldsm_x4(uint32_t* r, uint32_t addr) {
    asm volatile("ldmatrix.sync.aligned.m8n8.x4.shared.b16 {%0,%1,%2,%3}, [%4];"
                 : "=r"(r[0]), "=r"(r[1]), "=r"(r[2]), "=r"(r[3]) : "r"(addr));
}
__device__ __forceinline__ void ldsm_x4_t(uint32_t* r, uint32_t addr) {
    asm volatile("ldmatrix.sync.aligned.m8n8.x4.trans.shared.b16 {%0,%1,%2,%3}, [%4];"
                 : "=r"(r[0]), "=r"(r[1]), "=r"(r[2]), "=r"(r[3]) : "r"(addr));
}
__device__ __forceinline__ void ldsm_x2_t(uint32_t* r, uint32_t addr) {
    asm volatile("ldmatrix.sync.aligned.m8n8.x2.trans.shared.b16 {%0,%1}, [%2];"
                 : "=r"(r[0]), "=r"(r[1]) : "r"(addr));
}
// D = A(16x16 bf16) * B(16x8 bf16) + D (fp32)
__device__ __forceinline__ void mma16816(float* c, const uint32_t* a, const uint32_t* b) {
    asm volatile(
        "mma.sync.aligned.m16n8k16.row.col.f32.bf16.bf16.f32 "
        "{%0,%1,%2,%3}, {%4,%5,%6,%7}, {%8,%9}, {%0,%1,%2,%3};"
        : "+f"(c[0]), "+f"(c[1]), "+f"(c[2]), "+f"(c[3])
        : "r"(a[0]), "r"(a[1]), "r"(a[2]), "r"(a[3]), "r"(b[0]), "r"(b[1]));
}

// fp32 -> (hi, lo) bf16 split, packed as 2x u32 per float4
__device__ __forceinline__ void split4(float4 v, uint2& hp, uint2& lp) {
    __nv_bfloat16 hx = __float2bfloat16(v.x), hy = __float2bfloat16(v.y);
    __nv_bfloat16 hz = __float2bfloat16(v.z), hw = __float2bfloat16(v.w);
    __nv_bfloat16 lx = __float2bfloat16(v.x - __bfloat162float(hx));
    __nv_bfloat16 ly = __float2bfloat16(v.y - __bfloat162float(hy));
    __nv_bfloat16 lz = __float2bfloat16(v.z - __bfloat162float(hz));
    __nv_bfloat16 lw = __float2bfloat16(v.w - __bfloat162float(hw));
    hp.x = (uint32_t)__bfloat16_as_ushort(hx) | ((uint32_t)__bfloat16_as_ushort(hy) << 16);
    hp.y = (uint32_t)__bfloat16_as_ushort(hz) | ((uint32_t)__bfloat16_as_ushort(hw) << 16);
    lp.x = (uint32_t)__bfloat16_as_ushort(lx) | ((uint32_t)__bfloat16_as_ushort(ly) << 16);
    lp.y = (uint32_t)__bfloat16_as_ushort(lz) | ((uint32_t)__bfloat16_as_ushort(lw) << 16);
}
__device__ __forceinline__ void split2(float x, float y, uint32_t& hi, uint32_t& lo) {
    __nv_bfloat16 hx = __float2bfloat16(x), hy = __float2bfloat16(y);
    __nv_bfloat16 lx = __float2bfloat16(x - __bfloat162float(hx));
    __nv_bfloat16 ly = __float2bfloat16(y - __bfloat162float(hy));
    hi = (uint32_t)__bfloat16_as_ushort(hx) | ((uint32_t)__bfloat16_as_ushort(hy) << 16);
    lo = (uint32_t)__bfloat16_as_ushort(lx) | ((uint32_t)__bfloat16_as_ushort(ly) << 16);
}

// exp2 on the FMA pipe (MUFU is the softmax floor otherwise): deg-5 poly,
// |f|<=0.5, rel err ~2e-6. Input y expected <= 0 (clamped at -126).
__device__ __forceinline__ float exp2p(float y) {
    y = fmaxf(y, -126.0f);
    float k = rintf(y);
    float f = y - k;
    float p = 1.3333558146e-3f;
    p = fmaf(p, f, 9.6181291058e-3f);
    p = fmaf(p, f, 5.5504108664e-2f);
    p = fmaf(p, f, 2.4022650696e-1f);
    p = fmaf(p, f, 6.9314718056e-1f);
    p = fmaf(p, f, 1.0f);
    return p * __int_as_float(((int)k + 127) << 23);
}

// ===========================================================================
// HMMA bf16-split GEMM (unchanged from R7): C = A @ W + bias
// ===========================================================================
constexpr int KC = 32;
constexpr int SA = 40;
constexpr int SB = 136;
constexpr int A_TILE = 128 * SA;
constexpr int B_TILE = KC * SB;
constexpr int STAGE_ELEMS = 2 * A_TILE + 2 * B_TILE;
constexpr int SMEM_GEMM = 2 * STAGE_ELEMS * 2;

__global__ __launch_bounds__(256)
void tc_gemm(const float* __restrict__ A,
             const float* __restrict__ W0, const float* __restrict__ bias0, float* __restrict__ C0,
             const float* __restrict__ W1, const float* __restrict__ bias1, float* __restrict__ C1,
             int N, int K)
{
    const float* W   = (blockIdx.z == 0) ? W0    : W1;
    const float* bia = (blockIdx.z == 0) ? bias0 : bias1;
    float*       C   = (blockIdx.z == 0) ? C0    : C1;

    extern __shared__ unsigned short smu[];
    const int tid  = threadIdx.x;
    const int wid  = tid >> 5;
    const int lane = tid & 31;
    const int row0 = blockIdx.y * 128;
    const int col0 = blockIdx.x * 128;

    const int wm = wid >> 2;
    const int wn = wid & 3;
    const int la = lane & 15;
    const int lb = lane >> 4;

    uint32_t offA[4], offB[4];
#pragma unroll
    for (int mi = 0; mi < 4; ++mi)
        offA[mi] = (uint32_t)(((wm * 64 + mi * 16 + la) * SA + lb * 8) * 2);
#pragma unroll
    for (int ni = 0; ni < 4; ++ni)
        offB[ni] = (uint32_t)((la * SB + wn * 32 + ni * 8) * 2);

    const uint32_t sb = smem_u32(smu);
    float4 pvA[4], pvB[4];

    auto ldg_chunk = [&](int c) {
        const int kc = c * KC;
#pragma unroll
        for (int u = 0; u < 4; ++u) {
            int idx = u * 256 + tid;
            int r = idx >> 3, c4 = idx & 7;
            pvA[u] = *(const float4*)(A + (size_t)(row0 + r) * K + kc + c4 * 4);
            int k = idx >> 5, n4 = idx & 31;
            pvB[u] = *(const float4*)(W + (size_t)(kc + k) * N + col0 + n4 * 4);
        }
    };
    auto sts_chunk = [&](int stg) {
        unsigned short* Ah = smu + (size_t)stg * STAGE_ELEMS;
        unsigned short* Al = Ah + A_TILE;
        unsigned short* Bh = Al + A_TILE;
        unsigned short* Bl = Bh + B_TILE;
#pragma unroll
        for (int u = 0; u < 4; ++u) {
            int idx = u * 256 + tid;
            uint2 hp, lp;
            int r = idx >> 3, c4 = idx & 7;
            split4(pvA[u], hp, lp);
            *(uint2*)&Ah[r * SA + c4 * 4] = hp;
            *(uint2*)&Al[r * SA + c4 * 4] = lp;
            int k = idx >> 5, n4 = idx & 31;
            split4(pvB[u], hp, lp);
            *(uint2*)&Bh[k * SB + n4 * 4] = hp;
            *(uint2*)&Bl[k * SB + n4 * 4] = lp;
        }
    };

    float acc[4][4][4];
#pragma unroll
    for (int mi = 0; mi < 4; ++mi)
#pragma unroll
        for (int ni = 0; ni < 4; ++ni)
#pragma unroll
            for (int r = 0; r < 4; ++r) acc[mi][ni][r] = 0.0f;

    ldg_chunk(0);
    sts_chunk(0);
    __syncthreads();

    const int NCH = K / KC;
    for (int ci = 0; ci < NCH; ++ci) {
        const int cur = ci & 1;
        const bool more = (ci + 1 < NCH);
        if (more) ldg_chunk(ci + 1);

        const uint32_t bAh = sb + (uint32_t)(cur * STAGE_ELEMS) * 2;
        const uint32_t bAl = bAh + A_TILE * 2;
        const uint32_t bBh = bAl + A_TILE * 2;
        const uint32_t bBl = bBh + B_TILE * 2;

#pragma unroll
        for (int kk = 0; kk < 2; ++kk) {
            const uint32_t dA = (uint32_t)(kk * 16 * 2);
            const uint32_t dB = (uint32_t)(kk * 16 * SB * 2);
            uint32_t ah[4][4], al[4][4], bh[4][2], bl[4][2];
#pragma unroll
            for (int mi = 0; mi < 4; ++mi) {
                ldsm_x4(ah[mi], bAh + offA[mi] + dA);
                ldsm_x4(al[mi], bAl + offA[mi] + dA);
            }
#pragma unroll
            for (int ni = 0; ni < 4; ++ni) {
                ldsm_x2_t(bh[ni], bBh + offB[ni] + dB);
                ldsm_x2_t(bl[ni], bBl + offB[ni] + dB);
            }
#pragma unroll
            for (int mi = 0; mi < 4; ++mi)
#pragma unroll
                for (int ni = 0; ni < 4; ++ni)
                    mma16816(acc[mi][ni], ah[mi], bh[ni]);
#pragma unroll
            for (int mi = 0; mi < 4; ++mi)
#pragma unroll
                for (int ni = 0; ni < 4; ++ni)
                    mma16816(acc[mi][ni], ah[mi], bl[ni]);
#pragma unroll
            for (int mi = 0; mi < 4; ++mi)
#pragma unroll
                for (int ni = 0; ni < 4; ++ni)
                    mma16816(acc[mi][ni], al[mi], bh[ni]);
        }

        if (more) sts_chunk(cur ^ 1);
        __syncthreads();
    }

    const int g = lane >> 2, t = lane & 3;
#pragma unroll
    for (int mi = 0; mi < 4; ++mi) {
#pragma unroll
        for (int ni = 0; ni < 4; ++ni) {
            int row = row0 + wm * 64 + mi * 16 + g;
            int col = col0 + wn * 32 + ni * 8 + 2 * t;
            float b0v = bia[col], b1v = bia[col + 1];
            *(float2*)&C[(size_t)row * N + col] =
                make_float2(acc[mi][ni][0] + b0v, acc[mi][ni][1] + b1v);
            *(float2*)&C[(size_t)(row + 8) * N + col] =
                make_float2(acc[mi][ni][2] + b0v, acc[mi][ni][3] + b1v);
        }
    }
}

// ===========================================================================
// HMMA flash attention (bf16-split QK^T and PV, fp32 softmax, poly exp2).
// CTA: 128 q-rows x (head, batch). 8 warps x 16 q-rows. KV tile Bc=64.
// Q prescaled by 1/sqrt(HD), split hi/lo, kept in registers as A-frags.
// K smem [kv][hd] read as B via ldmatrix.x4 (non-trans; pair r0/r2, r1/r3).
// V smem [kv][hd] read as B via ldmatrix.x4.trans (pair r0/r1, r2/r3).
// P stays in registers (acc-frag == A-frag layout).
// ===========================================================================
constexpr int BQ = 128;
constexpr int BC = 64;
constexpr int FS = 136;                  // smem row stride (elems)
constexpr int QL_O = 128 * FS;           // Q lo offset (elems); Q hi at 0
constexpr int KL_O = 64 * FS;            // K lo;  K hi at 0
constexpr int VH_O = 2 * 64 * FS;        // V hi
constexpr int VL_O = 3 * 64 * FS;        // V lo
constexpr int SMEM_FLA = 2 * 128 * FS * 2;   // 69632 B

__global__ __launch_bounds__(256)
void flash_hmma(const float* __restrict__ mask, const float* __restrict__ Qg,
                const float* __restrict__ Kg,   const float* __restrict__ Vg,
                float* __restrict__ O)
{
    extern __shared__ unsigned short smu[];
    const uint32_t sb = smem_u32(smu);
    const int tid  = threadIdx.x;
    const int wid  = tid >> 5;
    const int lane = tid & 31;
    const int q0 = blockIdx.x * BQ;
    const int h  = blockIdx.y;
    const int b  = blockIdx.z;
    const int qr = wid * 16;
    const int g  = lane >> 2;
    const int t  = lane & 3;
    const float scale = 0.08838834764831845f;      // 1/sqrt(128)
    const float L2E   = 1.4426950408889634f;

    // ---- load Q tile, prescale, split into smem ----
#pragma unroll
    for (int u = 0; u < 16; ++u) {
        int idx = u * 256 + tid;
        int r = idx >> 5, c4 = idx & 31;
        float4 v = *(const float4*)(Qg + ((size_t)(b * S_ + q0 + r)) * D_ + h * HD_ + c4 * 4);
        v.x *= scale; v.y *= scale; v.z *= scale; v.w *= scale;
        uint2 hp, lp; split4(v, hp, lp);
        *(uint2*)&smu[r * FS + c4 * 4]        = hp;
        *(uint2*)&smu[QL_O + r * FS + c4 * 4] = lp;
    }
    __syncthreads();

    // ---- Q A-frags into registers (persist across all KV tiles) ----
    uint32_t ah[8][4], al[8][4];
#pragma unroll
    for (int ks = 0; ks < 8; ++ks) {
        uint32_t ad = sb + (uint32_t)((((qr + (lane & 15)) * FS) + ks * 16 + (lane >> 4) * 8) * 2);
        ldsm_x4(ah[ks], ad);
        ldsm_x4(al[ks], ad + QL_O * 2);
    }

    float m0 = -1e30f, m1 = -1e30f, l0 = 0.0f, l1 = 0.0f;
    float o[16][4];
#pragma unroll
    for (int nf = 0; nf < 16; ++nf)
#pragma unroll
        for (int r = 0; r < 4; ++r) o[nf][r] = 0.0f;

    for (int kv0 = 0; kv0 < S_; kv0 += BC) {
        __syncthreads();   // prior tile's smem reads (and Q-frag reads) done
        // ---- load K,V tile, split into smem ----
#pragma unroll
        for (int u = 0; u < 8; ++u) {
            int idx = u * 256 + tid;
            int r = idx >> 5, c4 = idx & 31;
            size_t go = ((size_t)(b * S_ + kv0 + r)) * HD_ + c4 * 4;
            uint2 hp, lp;
            float4 kv4 = *(const float4*)(Kg + go);
            split4(kv4, hp, lp);
            *(uint2*)&smu[r * FS + c4 * 4]        = hp;
            *(uint2*)&smu[KL_O + r * FS + c4 * 4] = lp;
            float4 vv4 = *(const float4*)(Vg + go);
            split4(vv4, hp, lp);
            *(uint2*)&smu[VH_O + r * FS + c4 * 4] = hp;
            *(uint2*)&smu[VL_O + r * FS + c4 * 4] = lp;
        }
        __syncthreads();

        // ---- S = Q @ K^T (split: hh + lh + hl) ----
        float s[8][4];
#pragma unroll
        for (int j = 0; j < 8; ++j)
#pragma unroll
            for (int r = 0; r < 4; ++r) s[j][r] = 0.0f;

#pragma unroll
        for (int ks = 0; ks < 8; ++ks) {
            uint32_t t4[4], kh[8][2];
#pragma unroll
            for (int gg = 0; gg < 4; ++gg) {
                uint32_t ad = sb + (uint32_t)((((gg * 16 + (lane & 15)) * FS) + ks * 16 + (lane >> 4) * 8) * 2);
                ldsm_x4(t4, ad);
                kh[2 * gg][0] = t4[0]; kh[2 * gg][1] = t4[2];
                kh[2 * gg + 1][0] = t4[1]; kh[2 * gg + 1][1] = t4[3];
            }
#pragma unroll
            for (int j = 0; j < 8; ++j) mma16816(s[j], ah[ks], kh[j]);
#pragma unroll
            for (int j = 0; j < 8; ++j) mma16816(s[j], al[ks], kh[j]);
            uint32_t kl[8][2];
#pragma unroll
            for (int gg = 0; gg < 4; ++gg) {
                uint32_t ad = sb + (uint32_t)((KL_O + (gg * 16 + (lane & 15)) * FS + ks * 16 + (lane >> 4) * 8) * 2);
                ldsm_x4(t4, ad);
                kl[2 * gg][0] = t4[0]; kl[2 * gg][1] = t4[2];
                kl[2 * gg + 1][0] = t4[1]; kl[2 * gg + 1][1] = t4[3];
            }
#pragma unroll
            for (int j = 0; j < 8; ++j) mma16816(s[j], ah[ks], kl[j]);
        }

        // ---- + mask ----
        const float* mp0 = mask + ((size_t)b * S_ + (q0 + qr + g)) * S_ + kv0 + 2 * t;
        const float* mp1 = mp0 + 8 * (size_t)S_;
#pragma unroll
        for (int j = 0; j < 8; ++j) {
            float2 u0 = *(const float2*)(mp0 + j * 8);
            float2 u1 = *(const float2*)(mp1 + j * 8);
            s[j][0] += u0.x; s[j][1] += u0.y;
            s[j][2] += u1.x; s[j][3] += u1.y;
        }

        // ---- online softmax (rows g and g+8; 4 lanes share a row) ----
        float mx0 = -1e30f, mx1 = -1e30f;
#pragma unroll
        for (int j = 0; j < 8; ++j) {
            mx0 = fmaxf(mx0, fmaxf(s[j][0], s[j][1]));
            mx1 = fmaxf(mx1, fmaxf(s[j][2], s[j][3]));
        }
        mx0 = fmaxf(mx0, __shfl_xor_sync(0xffffffffu, mx0, 1));
        mx0 = fmaxf(mx0, __shfl_xor_sync(0xffffffffu, mx0, 2));
        mx1 = fmaxf(mx1, __shfl_xor_sync(0xffffffffu, mx1, 1));
        mx1 = fmaxf(mx1, __shfl_xor_sync(0xffffffffu, mx1, 2));
        float nm0 = fmaxf(m0, mx0), nm1 = fmaxf(m1, mx1);
        float a0 = exp2p((m0 - nm0) * L2E);
        float a1 = exp2p((m1 - nm1) * L2E);
        m0 = nm0; m1 = nm1;
        float b0 = nm0 * L2E, b1 = nm1 * L2E;
        float nl0 = 0.0f, nl1 = 0.0f;
#pragma unroll
        for (int j = 0; j < 8; ++j) {
            s[j][0] = exp2p(fmaf(s[j][0], L2E, -b0));
            s[j][1] = exp2p(fmaf(s[j][1], L2E, -b0));
            s[j][2] = exp2p(fmaf(s[j][2], L2E, -b1));
            s[j][3] = exp2p(fmaf(s[j][3], L2E, -b1));
            nl0 += s[j][0] + s[j][1];
            nl1 += s[j][2] + s[j][3];
        }
        nl0 += __shfl_xor_sync(0xffffffffu, nl0, 1);
        nl0 += __shfl_xor_sync(0xffffffffu, nl0, 2);
        nl1 += __shfl_xor_sync(0xffffffffu, nl1, 1);
        nl1 += __shfl_xor_sync(0xffffffffu, nl1, 2);
        l0 = l0 * a0 + nl0;
        l1 = l1 * a1 + nl1;

        // ---- pack P into split A-frags (acc layout == A layout) ----
        uint32_t ph[4][4], pl[4][4];
#pragma unroll
        for (int k2 = 0; k2 < 4; ++k2) {
            split2(s[2 * k2][0],     s[2 * k2][1],     ph[k2][0], pl[k2][0]);
            split2(s[2 * k2][2],     s[2 * k2][3],     ph[k2][1], pl[k2][1]);
            split2(s[2 * k2 + 1][0], s[2 * k2 + 1][1], ph[k2][2], pl[k2][2]);
            split2(s[2 * k2 + 1][2], s[2 * k2 + 1][3], ph[k2][3], pl[k2][3]);
        }

        // ---- rescale O ----
#pragma unroll
        for (int nf = 0; nf < 16; ++nf) {
            o[nf][0] *= a0; o[nf][1] *= a0;
            o[nf][2] *= a1; o[nf][3] *= a1;
        }

        // ---- O += P @ V (split: ph*vh + pl*vh + ph*vl) ----
#pragma unroll
        for (int k2 = 0; k2 < 4; ++k2) {
#pragma unroll
            for (int half = 0; half < 2; ++half) {
                uint32_t t4[4], vh[8][2];
#pragma unroll
                for (int gi = 0; gi < 4; ++gi) {
                    int n0 = (half * 4 + gi) * 16;
                    uint32_t ad = sb + (uint32_t)((VH_O + (k2 * 16 + (lane & 15)) * FS + n0 + (lane >> 4) * 8) * 2);
                    ldsm_x4_t(t4, ad);
                    vh[2 * gi][0] = t4[0]; vh[2 * gi][1] = t4[1];
                    vh[2 * gi + 1][0] = t4[2]; vh[2 * gi + 1][1] = t4[3];
                }
#pragma unroll
                for (int f = 0; f < 8; ++f) mma16816(o[half * 8 + f], ph[k2], vh[f]);
#pragma unroll
                for (int f = 0; f < 8; ++f) mma16816(o[half * 8 + f], pl[k2], vh[f]);
                uint32_t vl[8][2];
#pragma unroll
                for (int gi = 0; gi < 4; ++gi) {
                    int n0 = (half * 4 + gi) * 16;
                    uint32_t ad = sb + (uint32_t)((VL_O + (k2 * 16 + (lane & 15)) * FS + n0 + (lane >> 4) * 8) * 2);
                    ldsm_x4_t(t4, ad);
                    vl[2 * gi][0] = t4[0]; vl[2 * gi][1] = t4[1];
                    vl[2 * gi + 1][0] = t4[2]; vl[2 * gi + 1][1] = t4[3];
                }
#pragma unroll
                for (int f = 0; f < 8; ++f) mma16816(o[half * 8 + f], ph[k2], vl[f]);
            }
        }
    }

    // ---- finalize: O / l -> gmem [b, q, h*HD + d] ----
    float il0 = 1.0f / l0, il1 = 1.0f / l1;
    size_t base0 = ((size_t)(b * S_ + q0 + qr + g)) * D_ + h * HD_ + 2 * t;
    size_t base1 = base0 + 8 * (size_t)D_;
#pragma unroll
    for (int nf = 0; nf < 16; ++nf) {
        *(float2*)&O[base0 + nf * 8] = make_float2(o[nf][0] * il0, o[nf][1] * il0);
        *(float2*)&O[base1 + nf * 8] = make_float2(o[nf][2] * il1, o[nf][3] * il1);
    }
}

// ---------------------------------------------------------------------------
extern "C" void kernel_launch(void* const* d_in, const int* in_sizes, int n_in,
                              void* d_out, int out_size)
{
    (void)in_sizes; (void)n_in; (void)out_size;
    const float* x    = (const float*)d_in[0];
    const float* mask = (const float*)d_in[1];
    const float* wq_w = (const float*)d_in[2];
    const float* wq_b = (const float*)d_in[3];
    const float* wk_w = (const float*)d_in[4];
    const float* wk_b = (const float*)d_in[5];
    const float* wv_w = (const float*)d_in[6];
    const float* wv_b = (const float*)d_in[7];
    const float* wo_w = (const float*)d_in[8];
    const float* wo_b = (const float*)d_in[9];
    float* out = (float*)d_out;

    float *qb, *kb, *vb, *ab;
    cudaGetSymbolAddress((void**)&qb, g_q);
    cudaGetSymbolAddress((void**)&kb, g_k);
    cudaGetSymbolAddress((void**)&vb, g_v);
    cudaGetSymbolAddress((void**)&ab, g_att);

    cudaFuncSetAttribute(tc_gemm,    cudaFuncAttributeMaxDynamicSharedMemorySize, SMEM_GEMM);
    cudaFuncSetAttribute(flash_hmma, cudaFuncAttributeMaxDynamicSharedMemorySize, SMEM_FLA);

    dim3 blk(256);
    // Q = x @ wq + bq           [4096,2048] x [2048,2048]
    tc_gemm<<<dim3(16, 32, 1), blk, SMEM_GEMM>>>(x, wq_w, wq_b, qb, wq_w, wq_b, qb, D_, D_);
    // K,V = x @ wk/wv + b       [4096,2048] x [2048,128], z selects K vs V
    tc_gemm<<<dim3(1, 32, 2), blk, SMEM_GEMM>>>(x, wk_w, wk_b, kb, wv_w, wv_b, vb, HD_, D_);
    // attention (HMMA flash)
    flash_hmma<<<dim3(S_ / BQ, H_, B_), blk, SMEM_FLA>>>(mask, qb, kb, vb, ab);
    // out = att @ wo + bo
    tc_gemm<<<dim3(16, 32, 1), blk, SMEM_GEMM>>>(ab, wo_w, wo_b, out, wo_w, wo_b, out, D_, D_);
}

// round 9
// speedup vs baseline: 2.8100x; 1.2753x over previous
#include <cuda_runtime.h>
#include <cuda_bf16.h>
#include <cstdint>
#include <math.h>

// Problem constants
constexpr int B_  = 2;
constexpr int S_  = 2048;
constexpr int D_  = 2048;
constexpr int H_  = 16;
constexpr int HD_ = 128;

// ---- pre-split bf16 scratch (device globals; no allocation allowed) ----
__device__ __nv_bfloat16 g_xh [(size_t)B_ * S_ * D_], g_xl [(size_t)B_ * S_ * D_];
__device__ __nv_bfloat16 g_wqh[(size_t)D_ * D_],      g_wql[(size_t)D_ * D_];
__device__ __nv_bfloat16 g_wkh[(size_t)D_ * HD_],     g_wkl[(size_t)D_ * HD_];
__device__ __nv_bfloat16 g_wvh[(size_t)D_ * HD_],     g_wvl[(size_t)D_ * HD_];
__device__ __nv_bfloat16 g_woh[(size_t)D_ * D_],      g_wol[(size_t)D_ * D_];
__device__ __nv_bfloat16 g_qh [(size_t)B_ * S_ * D_], g_ql [(size_t)B_ * S_ * D_];
__device__ __nv_bfloat16 g_kh [(size_t)B_ * S_ * HD_], g_kl [(size_t)B_ * S_ * HD_];
__device__ __nv_bfloat16 g_vh [(size_t)B_ * S_ * HD_], g_vl [(size_t)B_ * S_ * HD_];
__device__ __nv_bfloat16 g_ath[(size_t)B_ * S_ * D_], g_atl[(size_t)B_ * S_ * D_];

// ===========================================================================
// PTX helpers — baseline ISA only (mma.sync sm_80+, ldmatrix, cp.async).
// ===========================================================================
__device__ __forceinline__ uint32_t smem_u32(const void* p) {
    uint32_t a;
    asm("{ .reg .u64 t; cvta.to.shared.u64 t, %1; cvt.u32.u64 %0, t; }"
        : "=r"(a) : "l"(p));
    return a;
}
__device__ __forceinline__ void ldsm_x4(uint32_t* r, uint32_t addr) {
    asm volatile("ldmatrix.sync.aligned.m8n8.x4.shared.b16 {%0,%1,%2,%3}, [%4];"
                 : "=r"(r[0]), "=r"(r[1]), "=r"(r[2]), "=r"(r[3]) : "r"(addr));
}
__device__ __forceinline__ void ldsm_x4_t(uint32_t* r, uint32_t addr) {
    asm volatile("ldmatrix.sync.aligned.m8n8.x4.trans.shared.b16 {%0,%1,%2,%3}, [%4];"
                 : "=r"(r[0]), "=r"(r[1]), "=r"(r[2]), "=r"(r[3]) : "r"(addr));
}
__device__ __forceinline__ void ldsm_x2_t(uint32_t* r, uint32_t addr) {
    asm volatile("ldmatrix.sync.aligned.m8n8.x2.trans.shared.b16 {%0,%1}, [%2];"
                 : "=r"(r[0]), "=r"(r[1]) : "r"(addr));
}
__device__ __forceinline__ void mma16816(float* c, const uint32_t* a, const uint32_t* b) {
    asm volatile(
        "mma.sync.aligned.m16n8k16.row.col.f32.bf16.bf16.f32 "
        "{%0,%1,%2,%3}, {%4,%5,%6,%7}, {%8,%9}, {%0,%1,%2,%3};"
        : "+f"(c[0]), "+f"(c[1]), "+f"(c[2]), "+f"(c[3])
        : "r"(a[0]), "r"(a[1]), "r"(a[2]), "r"(a[3]), "r"(b[0]), "r"(b[1]));
}
__device__ __forceinline__ void cp16(uint32_t dst, const void* src) {
    asm volatile("cp.async.cg.shared.global [%0], [%1], 16;" :: "r"(dst), "l"(src));
}
#define CP_COMMIT() asm volatile("cp.async.commit_group;" ::: "memory")
template<int N> __device__ __forceinline__ void cp_wait() {
    asm volatile("cp.async.wait_group %0;" :: "n"(N) : "memory");
}

__device__ __forceinline__ void split4(float4 v, uint2& hp, uint2& lp) {
    __nv_bfloat16 hx = __float2bfloat16(v.x), hy = __float2bfloat16(v.y);
    __nv_bfloat16 hz = __float2bfloat16(v.z), hw = __float2bfloat16(v.w);
    __nv_bfloat16 lx = __float2bfloat16(v.x - __bfloat162float(hx));
    __nv_bfloat16 ly = __float2bfloat16(v.y - __bfloat162float(hy));
    __nv_bfloat16 lz = __float2bfloat16(v.z - __bfloat162float(hz));
    __nv_bfloat16 lw = __float2bfloat16(v.w - __bfloat162float(hw));
    hp.x = (uint32_t)__bfloat16_as_ushort(hx) | ((uint32_t)__bfloat16_as_ushort(hy) << 16);
    hp.y = (uint32_t)__bfloat16_as_ushort(hz) | ((uint32_t)__bfloat16_as_ushort(hw) << 16);
    lp.x = (uint32_t)__bfloat16_as_ushort(lx) | ((uint32_t)__bfloat16_as_ushort(ly) << 16);
    lp.y = (uint32_t)__bfloat16_as_ushort(lz) | ((uint32_t)__bfloat16_as_ushort(lw) << 16);
}
__device__ __forceinline__ void split2(float x, float y, uint32_t& hi, uint32_t& lo) {
    __nv_bfloat16 hx = __float2bfloat16(x), hy = __float2bfloat16(y);
    __nv_bfloat16 lx = __float2bfloat16(x - __bfloat162float(hx));
    __nv_bfloat16 ly = __float2bfloat16(y - __bfloat162float(hy));
    hi = (uint32_t)__bfloat16_as_ushort(hx) | ((uint32_t)__bfloat16_as_ushort(hy) << 16);
    lo = (uint32_t)__bfloat16_as_ushort(lx) | ((uint32_t)__bfloat16_as_ushort(ly) << 16);
}

// exp2 on the FMA pipe: deg-5 poly, rel err ~2e-6.
__device__ __forceinline__ float exp2p(float y) {
    y = fmaxf(y, -126.0f);
    float k = rintf(y);
    float f = y - k;
    float p = 1.3333558146e-3f;
    p = fmaf(p, f, 9.6181291058e-3f);
    p = fmaf(p, f, 5.5504108664e-2f);
    p = fmaf(p, f, 2.4022650696e-1f);
    p = fmaf(p, f, 6.9314718056e-1f);
    p = fmaf(p, f, 1.0f);
    return p * __int_as_float(((int)k + 127) << 23);
}

// ===========================================================================
// Prepass: fp32 -> (hi, lo) bf16 split, elementwise. n % 4 == 0.
// ===========================================================================
__global__ void split_arr(const float* __restrict__ src,
                          __nv_bfloat16* __restrict__ h, __nv_bfloat16* __restrict__ l)
{
    int i = (blockIdx.x * blockDim.x + threadIdx.x) * 4;
    float4 v = *(const float4*)(src + i);
    uint2 hp, lp;
    split4(v, hp, lp);
    *(uint2*)(h + i) = hp;
    *(uint2*)(l + i) = lp;
}

// ===========================================================================
// tc_gemm2: C = A @ W + bias, pre-split bf16 inputs, cp.async 3-stage pipe.
// CTA tile 128x128, K chunk 32, 8 warps (2m x 4n), warp tile 64x32.
// D += Ah*Bh + Ah*Bl + Al*Bh (fp32 acc). Epilogue: fp32 out (Cf != null)
// or split-bf16 out scaled by oscale (Ch/Cl). blockIdx.z selects operand set.
// ===========================================================================
constexpr int KC2  = 32;
constexpr int SAe  = 40;                   // A smem stride (elems, 80B: ldsm conflict-free)
constexpr int SBe  = 136;                  // B smem stride (elems, 272B)
constexpr int AL_E = 128 * SAe;            // 5120
constexpr int BH_E = 2 * 128 * SAe;        // 10240
constexpr int BL_E = BH_E + KC2 * SBe;     // 14592
constexpr int STG_E = BL_E + KC2 * SBe;    // 18944 elems/stage
constexpr int SMEM_G2 = 3 * STG_E * 2;     // 113664 B

__global__ __launch_bounds__(256)
void tc_gemm2(const __nv_bfloat16* __restrict__ Agh, const __nv_bfloat16* __restrict__ Agl,
              const __nv_bfloat16* __restrict__ Bh0, const __nv_bfloat16* __restrict__ Bl0,
              const float* __restrict__ bias0, float* Cf0,
              __nv_bfloat16* Ch0, __nv_bfloat16* Cl0,
              const __nv_bfloat16* __restrict__ Bh1, const __nv_bfloat16* __restrict__ Bl1,
              const float* __restrict__ bias1, float* Cf1,
              __nv_bfloat16* Ch1, __nv_bfloat16* Cl1,
              int N, int K, float oscale)
{
    const __nv_bfloat16* Bgh = (blockIdx.z == 0) ? Bh0 : Bh1;
    const __nv_bfloat16* Bgl = (blockIdx.z == 0) ? Bl0 : Bl1;
    const float* bia = (blockIdx.z == 0) ? bias0 : bias1;
    float* Cf        = (blockIdx.z == 0) ? Cf0 : Cf1;
    __nv_bfloat16* Ch = (blockIdx.z == 0) ? Ch0 : Ch1;
    __nv_bfloat16* Cl = (blockIdx.z == 0) ? Cl0 : Cl1;

    extern __shared__ unsigned short smu[];
    const uint32_t sb = smem_u32(smu);
    const int tid  = threadIdx.x;
    const int wid  = tid >> 5;
    const int lane = tid & 31;
    const int row0 = blockIdx.y * 128;
    const int col0 = blockIdx.x * 128;

    const int wm = wid >> 2;
    const int wn = wid & 3;
    const int la = lane & 15;
    const int lb = lane >> 4;

    uint32_t offA[4], offB[4];
#pragma unroll
    for (int mi = 0; mi < 4; ++mi)
        offA[mi] = (uint32_t)(((wm * 64 + mi * 16 + la) * SAe + lb * 8) * 2);
#pragma unroll
    for (int ni = 0; ni < 4; ++ni)
        offB[ni] = (uint32_t)((la * SBe + wn * 32 + ni * 8) * 2);

    // cp.async chunk loader: 8x 16B per thread per stage
    auto issue = [&](int c, int stg) {
        const int kc = c * KC2;
        const uint32_t sbase = sb + (uint32_t)(stg * STG_E) * 2;
#pragma unroll
        for (int u = 0; u < 2; ++u) {           // A: 128 rows x 4 chunks (hi & lo)
            int ci2 = u * 256 + tid;
            int r = ci2 >> 2, p = ci2 & 3;
            uint32_t doff = (uint32_t)((r * SAe + p * 8) * 2);
            const size_t gsrc = (size_t)(row0 + r) * K + kc + p * 8;
            cp16(sbase + doff, Agh + gsrc);
            cp16(sbase + AL_E * 2 + doff, Agl + gsrc);
        }
#pragma unroll
        for (int u = 0; u < 2; ++u) {           // B: 32 rows x 16 chunks (hi & lo)
            int ci2 = u * 256 + tid;
            int k = ci2 >> 4, p = ci2 & 15;
            uint32_t doff = (uint32_t)((k * SBe + p * 8) * 2);
            const size_t gsrc = (size_t)(kc + k) * N + col0 + p * 8;
            cp16(sbase + BH_E * 2 + doff, Bgh + gsrc);
            cp16(sbase + BL_E * 2 + doff, Bgl + gsrc);
        }
    };

    float acc[4][4][4];
#pragma unroll
    for (int mi = 0; mi < 4; ++mi)
#pragma unroll
        for (int ni = 0; ni < 4; ++ni)
#pragma unroll
            for (int r = 0; r < 4; ++r) acc[mi][ni][r] = 0.0f;

    issue(0, 0); CP_COMMIT();
    issue(1, 1); CP_COMMIT();

    const int NCH = K / KC2;
    for (int ci = 0; ci < NCH; ++ci) {
        cp_wait<1>();                 // chunk ci's group complete
        __syncthreads();              // all warps done reading stage (ci-1)%3
        if (ci + 2 < NCH) { issue(ci + 2, (ci + 2) % 3); CP_COMMIT(); }

        const uint32_t bAh = sb + (uint32_t)((ci % 3) * STG_E) * 2;
        const uint32_t bAl = bAh + AL_E * 2;
        const uint32_t bBh = sb + (uint32_t)((ci % 3) * STG_E + BH_E) * 2;
        const uint32_t bBl = bBh + (BL_E - BH_E) * 2;

#pragma unroll
        for (int kk = 0; kk < 2; ++kk) {
            const uint32_t dA = (uint32_t)(kk * 16 * 2);
            const uint32_t dB = (uint32_t)(kk * 16 * SBe * 2);
            uint32_t ah[4][4], al[4][4], bh[4][2], bl[4][2];
#pragma unroll
            for (int mi = 0; mi < 4; ++mi) {
                ldsm_x4(ah[mi], bAh + offA[mi] + dA);
                ldsm_x4(al[mi], bAl + offA[mi] + dA);
            }
#pragma unroll
            for (int ni = 0; ni < 4; ++ni) {
                ldsm_x2_t(bh[ni], bBh + offB[ni] + dB);
                ldsm_x2_t(bl[ni], bBl + offB[ni] + dB);
            }
#pragma unroll
            for (int mi = 0; mi < 4; ++mi)
#pragma unroll
                for (int ni = 0; ni < 4; ++ni)
                    mma16816(acc[mi][ni], ah[mi], bh[ni]);
#pragma unroll
            for (int mi = 0; mi < 4; ++mi)
#pragma unroll
                for (int ni = 0; ni < 4; ++ni)
                    mma16816(acc[mi][ni], ah[mi], bl[ni]);
#pragma unroll
            for (int mi = 0; mi < 4; ++mi)
#pragma unroll
                for (int ni = 0; ni < 4; ++ni)
                    mma16816(acc[mi][ni], al[mi], bh[ni]);
        }
    }

    // ---- epilogue ----
    const int g = lane >> 2, t = lane & 3;
    if (Cf) {
#pragma unroll
        for (int mi = 0; mi < 4; ++mi)
#pragma unroll
            for (int ni = 0; ni < 4; ++ni) {
                int row = row0 + wm * 64 + mi * 16 + g;
                int col = col0 + wn * 32 + ni * 8 + 2 * t;
                float b0v = bia[col], b1v = bia[col + 1];
                *(float2*)&Cf[(size_t)row * N + col] =
                    make_float2(acc[mi][ni][0] + b0v, acc[mi][ni][1] + b1v);
                *(float2*)&Cf[(size_t)(row + 8) * N + col] =
                    make_float2(acc[mi][ni][2] + b0v, acc[mi][ni][3] + b1v);
            }
    } else {
#pragma unroll
        for (int mi = 0; mi < 4; ++mi)
#pragma unroll
            for (int ni = 0; ni < 4; ++ni) {
                int row = row0 + wm * 64 + mi * 16 + g;
                int col = col0 + wn * 32 + ni * 8 + 2 * t;
                float b0v = bia[col], b1v = bia[col + 1];
                uint32_t hi, lo;
                split2((acc[mi][ni][0] + b0v) * oscale, (acc[mi][ni][1] + b1v) * oscale, hi, lo);
                *(uint32_t*)(Ch + (size_t)row * N + col) = hi;
                *(uint32_t*)(Cl + (size_t)row * N + col) = lo;
                split2((acc[mi][ni][2] + b0v) * oscale, (acc[mi][ni][3] + b1v) * oscale, hi, lo);
                *(uint32_t*)(Ch + (size_t)(row + 8) * N + col) = hi;
                *(uint32_t*)(Cl + (size_t)(row + 8) * N + col) = lo;
            }
    }
}

// ===========================================================================
// flash_hmma2: pre-split bf16 Q/K/V via cp.async, split bf16 att output.
// CTA: 128 q-rows x (head, batch); 8 warps x 16 q-rows; KV tile Bc=64,
// 2-stage cp.async pipeline, one __syncthreads per tile.
// ===========================================================================
constexpr int FSe   = 136;
constexpr int QL_E  = 128 * FSe;            // 17408 (Q hi at 0)
constexpr int ST0_E = 2 * 128 * FSe;        // 34816: stage area start
constexpr int KST_E = 4 * 64 * FSe;         // 34816 per stage (Kh,Kl,Vh,Vl)
constexpr int KL_S  = 64 * FSe;             // 8704
constexpr int VH_S  = 2 * 64 * FSe;         // 17408
constexpr int VL_S  = 3 * 64 * FSe;         // 26112
constexpr int SMEM_FL2 = (ST0_E + 2 * KST_E) * 2;   // 208896 B

__global__ __launch_bounds__(256)
void flash_hmma2(const float* __restrict__ mask,
                 const __nv_bfloat16* __restrict__ qh, const __nv_bfloat16* __restrict__ ql,
                 const __nv_bfloat16* __restrict__ kh, const __nv_bfloat16* __restrict__ kl,
                 const __nv_bfloat16* __restrict__ vh, const __nv_bfloat16* __restrict__ vl,
                 __nv_bfloat16* __restrict__ ath, __nv_bfloat16* __restrict__ atl)
{
    extern __shared__ unsigned short smu[];
    const uint32_t sb = smem_u32(smu);
    const int tid  = threadIdx.x;
    const int wid  = tid >> 5;
    const int lane = tid & 31;
    const int q0 = blockIdx.x * 128;
    const int h  = blockIdx.y;
    const int b  = blockIdx.z;
    const int qr = wid * 16;
    const int g  = lane >> 2;
    const int t  = lane & 3;
    const int la = lane & 15;
    const int lb = lane >> 4;
    const float L2E = 1.4426950408889634f;

    // ---- Q tile (pre-split, pre-scaled) via cp.async ----
#pragma unroll
    for (int u = 0; u < 8; ++u) {
        int ci2 = u * 256 + tid;
        int r = ci2 >> 4, p = ci2 & 15;
        const size_t gsrc = ((size_t)(b * S_ + q0 + r)) * D_ + h * HD_ + p * 8;
        uint32_t doff = (uint32_t)((r * FSe + p * 8) * 2);
        cp16(sb + doff, qh + gsrc);
        cp16(sb + QL_E * 2 + doff, ql + gsrc);
    }
    CP_COMMIT();

    // KV tile loader
    auto issueKV = [&](int c, int stg) {
        const int kv0 = c * 64;
        const uint32_t sbase = sb + (uint32_t)(ST0_E + stg * KST_E) * 2;
#pragma unroll
        for (int u = 0; u < 4; ++u) {
            int ci2 = u * 256 + tid;
            int r = ci2 >> 4, p = ci2 & 15;
            const size_t gsrc = ((size_t)(b * S_ + kv0 + r)) * HD_ + p * 8;
            uint32_t doff = (uint32_t)((r * FSe + p * 8) * 2);
            cp16(sbase + doff, kh + gsrc);
            cp16(sbase + KL_S * 2 + doff, kl + gsrc);
            cp16(sbase + VH_S * 2 + doff, vh + gsrc);
            cp16(sbase + VL_S * 2 + doff, vl + gsrc);
        }
    };

    issueKV(0, 0); CP_COMMIT();
    cp_wait<1>();           // Q group done
    __syncthreads();

    // ---- Q A-frags to registers (persist) ----
    uint32_t ah[8][4], al[8][4];
#pragma unroll
    for (int ks = 0; ks < 8; ++ks) {
        uint32_t ad = sb + (uint32_t)(((qr + la) * FSe + ks * 16 + lb * 8) * 2);
        ldsm_x4(ah[ks], ad);
        ldsm_x4(al[ks], ad + QL_E * 2);
    }

    float m0 = -1e30f, m1 = -1e30f, l0 = 0.0f, l1 = 0.0f;
    float o[16][4];
#pragma unroll
    for (int nf = 0; nf < 16; ++nf)
#pragma unroll
        for (int r = 0; r < 4; ++r) o[nf][r] = 0.0f;

    constexpr int NT = S_ / 64;
    for (int ci = 0; ci < NT; ++ci) {
        cp_wait<0>();
        __syncthreads();
        if (ci + 1 < NT) { issueKV(ci + 1, (ci + 1) & 1); CP_COMMIT(); }

        const int kv0 = ci * 64;
        const uint32_t sK = sb + (uint32_t)(ST0_E + (ci & 1) * KST_E) * 2;

        // ---- S = Q @ K^T (hh + lh + hl) ----
        float s[8][4];
#pragma unroll
        for (int j = 0; j < 8; ++j)
#pragma unroll
            for (int r = 0; r < 4; ++r) s[j][r] = 0.0f;

#pragma unroll
        for (int ks = 0; ks < 8; ++ks) {
            uint32_t t4[4], khf[8][2];
#pragma unroll
            for (int gg = 0; gg < 4; ++gg) {
                uint32_t ad = sK + (uint32_t)(((gg * 16 + la) * FSe + ks * 16 + lb * 8) * 2);
                ldsm_x4(t4, ad);
                khf[2 * gg][0] = t4[0]; khf[2 * gg][1] = t4[2];
                khf[2 * gg + 1][0] = t4[1]; khf[2 * gg + 1][1] = t4[3];
            }
#pragma unroll
            for (int j = 0; j < 8; ++j) mma16816(s[j], ah[ks], khf[j]);
#pragma unroll
            for (int j = 0; j < 8; ++j) mma16816(s[j], al[ks], khf[j]);
            uint32_t klf[8][2];
#pragma unroll
            for (int gg = 0; gg < 4; ++gg) {
                uint32_t ad = sK + (uint32_t)((KL_S + (gg * 16 + la) * FSe + ks * 16 + lb * 8) * 2);
                ldsm_x4(t4, ad);
                klf[2 * gg][0] = t4[0]; klf[2 * gg][1] = t4[2];
                klf[2 * gg + 1][0] = t4[1]; klf[2 * gg + 1][1] = t4[3];
            }
#pragma unroll
            for (int j = 0; j < 8; ++j) mma16816(s[j], ah[ks], klf[j]);
        }

        // ---- + mask ----
        const float* mp0 = mask + ((size_t)b * S_ + (q0 + qr + g)) * S_ + kv0 + 2 * t;
        const float* mp1 = mp0 + 8 * (size_t)S_;
#pragma unroll
        for (int j = 0; j < 8; ++j) {
            float2 u0 = *(const float2*)(mp0 + j * 8);
            float2 u1 = *(const float2*)(mp1 + j * 8);
            s[j][0] += u0.x; s[j][1] += u0.y;
            s[j][2] += u1.x; s[j][3] += u1.y;
        }

        // ---- online softmax ----
        float mx0 = -1e30f, mx1 = -1e30f;
#pragma unroll
        for (int j = 0; j < 8; ++j) {
            mx0 = fmaxf(mx0, fmaxf(s[j][0], s[j][1]));
            mx1 = fmaxf(mx1, fmaxf(s[j][2], s[j][3]));
        }
        mx0 = fmaxf(mx0, __shfl_xor_sync(0xffffffffu, mx0, 1));
        mx0 = fmaxf(mx0, __shfl_xor_sync(0xffffffffu, mx0, 2));
        mx1 = fmaxf(mx1, __shfl_xor_sync(0xffffffffu, mx1, 1));
        mx1 = fmaxf(mx1, __shfl_xor_sync(0xffffffffu, mx1, 2));
        float nm0 = fmaxf(m0, mx0), nm1 = fmaxf(m1, mx1);
        float a0 = exp2p((m0 - nm0) * L2E);
        float a1 = exp2p((m1 - nm1) * L2E);
        m0 = nm0; m1 = nm1;
        float b0 = nm0 * L2E, b1 = nm1 * L2E;
        float nl0 = 0.0f, nl1 = 0.0f;
#pragma unroll
        for (int j = 0; j < 8; ++j) {
            s[j][0] = exp2p(fmaf(s[j][0], L2E, -b0));
            s[j][1] = exp2p(fmaf(s[j][1], L2E, -b0));
            s[j][2] = exp2p(fmaf(s[j][2], L2E, -b1));
            s[j][3] = exp2p(fmaf(s[j][3], L2E, -b1));
            nl0 += s[j][0] + s[j][1];
            nl1 += s[j][2] + s[j][3];
        }
        nl0 += __shfl_xor_sync(0xffffffffu, nl0, 1);
        nl0 += __shfl_xor_sync(0xffffffffu, nl0, 2);
        nl1 += __shfl_xor_sync(0xffffffffu, nl1, 1);
        nl1 += __shfl_xor_sync(0xffffffffu, nl1, 2);
        l0 = l0 * a0 + nl0;
        l1 = l1 * a1 + nl1;

        // ---- P -> split A-frags ----
        uint32_t ph[4][4], pl[4][4];
#pragma unroll
        for (int k2 = 0; k2 < 4; ++k2) {
            split2(s[2 * k2][0],     s[2 * k2][1],     ph[k2][0], pl[k2][0]);
            split2(s[2 * k2][2],     s[2 * k2][3],     ph[k2][1], pl[k2][1]);
            split2(s[2 * k2 + 1][0], s[2 * k2 + 1][1], ph[k2][2], pl[k2][2]);
            split2(s[2 * k2 + 1][2], s[2 * k2 + 1][3], ph[k2][3], pl[k2][3]);
        }

        // ---- rescale O ----
#pragma unroll
        for (int nf = 0; nf < 16; ++nf) {
            o[nf][0] *= a0; o[nf][1] *= a0;
            o[nf][2] *= a1; o[nf][3] *= a1;
        }

        // ---- O += P @ V (ph*vh + pl*vh + ph*vl) ----
#pragma unroll
        for (int k2 = 0; k2 < 4; ++k2) {
#pragma unroll
            for (int half = 0; half < 2; ++half) {
                uint32_t t4[4], vhf[8][2];
#pragma unroll
                for (int gi = 0; gi < 4; ++gi) {
                    int n0 = (half * 4 + gi) * 16;
                    uint32_t ad = sK + (uint32_t)((VH_S + (k2 * 16 + la) * FSe + n0 + lb * 8) * 2);
                    ldsm_x4_t(t4, ad);
                    vhf[2 * gi][0] = t4[0]; vhf[2 * gi][1] = t4[1];
                    vhf[2 * gi + 1][0] = t4[2]; vhf[2 * gi + 1][1] = t4[3];
                }
#pragma unroll
                for (int f = 0; f < 8; ++f) mma16816(o[half * 8 + f], ph[k2], vhf[f]);
#pragma unroll
                for (int f = 0; f < 8; ++f) mma16816(o[half * 8 + f], pl[k2], vhf[f]);
                uint32_t vlf[8][2];
#pragma unroll
                for (int gi = 0; gi < 4; ++gi) {
                    int n0 = (half * 4 + gi) * 16;
                    uint32_t ad = sK + (uint32_t)((VL_S + (k2 * 16 + la) * FSe + n0 + lb * 8) * 2);
                    ldsm_x4_t(t4, ad);
                    vlf[2 * gi][0] = t4[0]; vlf[2 * gi][1] = t4[1];
                    vlf[2 * gi + 1][0] = t4[2]; vlf[2 * gi + 1][1] = t4[3];
                }
#pragma unroll
                for (int f = 0; f < 8; ++f) mma16816(o[half * 8 + f], ph[k2], vlf[f]);
            }
        }
    }

    // ---- finalize: O / l -> split bf16 att ----
    float il0 = 1.0f / l0, il1 = 1.0f / l1;
    size_t base0 = ((size_t)(b * S_ + q0 + qr + g)) * D_ + h * HD_ + 2 * t;
    size_t base1 = base0 + 8 * (size_t)D_;
#pragma unroll
    for (int nf = 0; nf < 16; ++nf) {
        uint32_t hi, lo;
        split2(o[nf][0] * il0, o[nf][1] * il0, hi, lo);
        *(uint32_t*)(ath + base0 + nf * 8) = hi;
        *(uint32_t*)(atl + base0 + nf * 8) = lo;
        split2(o[nf][2] * il1, o[nf][3] * il1, hi, lo);
        *(uint32_t*)(ath + base1 + nf * 8) = hi;
        *(uint32_t*)(atl + base1 + nf * 8) = lo;
    }
}

// ---------------------------------------------------------------------------
extern "C" void kernel_launch(void* const* d_in, const int* in_sizes, int n_in,
                              void* d_out, int out_size)
{
    (void)in_sizes; (void)n_in; (void)out_size;
    const float* x    = (const float*)d_in[0];
    const float* mask = (const float*)d_in[1];
    const float* wq_w = (const float*)d_in[2];
    const float* wq_b = (const float*)d_in[3];
    const float* wk_w = (const float*)d_in[4];
    const float* wk_b = (const float*)d_in[5];
    const float* wv_w = (const float*)d_in[6];
    const float* wv_b = (const float*)d_in[7];
    const float* wo_w = (const float*)d_in[8];
    const float* wo_b = (const float*)d_in[9];
    float* out = (float*)d_out;

    __nv_bfloat16 *xh, *xl, *wqh, *wql, *wkh, *wkl, *wvh, *wvl, *woh, *wol;
    __nv_bfloat16 *qh, *ql, *kh, *kl, *vh, *vl, *ath, *atl;
    cudaGetSymbolAddress((void**)&xh,  g_xh);  cudaGetSymbolAddress((void**)&xl,  g_xl);
    cudaGetSymbolAddress((void**)&wqh, g_wqh); cudaGetSymbolAddress((void**)&wql, g_wql);
    cudaGetSymbolAddress((void**)&wkh, g_wkh); cudaGetSymbolAddress((void**)&wkl, g_wkl);
    cudaGetSymbolAddress((void**)&wvh, g_wvh); cudaGetSymbolAddress((void**)&wvl, g_wvl);
    cudaGetSymbolAddress((void**)&woh, g_woh); cudaGetSymbolAddress((void**)&wol, g_wol);
    cudaGetSymbolAddress((void**)&qh,  g_qh);  cudaGetSymbolAddress((void**)&ql,  g_ql);
    cudaGetSymbolAddress((void**)&kh,  g_kh);  cudaGetSymbolAddress((void**)&kl,  g_kl);
    cudaGetSymbolAddress((void**)&vh,  g_vh);  cudaGetSymbolAddress((void**)&vl,  g_vl);
    cudaGetSymbolAddress((void**)&ath, g_ath); cudaGetSymbolAddress((void**)&atl, g_atl);

    cudaFuncSetAttribute(tc_gemm2,    cudaFuncAttributeMaxDynamicSharedMemorySize, SMEM_G2);
    cudaFuncSetAttribute(flash_hmma2, cudaFuncAttributeMaxDynamicSharedMemorySize, SMEM_FL2);

    const float scale = 0.08838834764831845f;  // 1/sqrt(128)
    dim3 blk(256);

    // prepass: split fp32 -> bf16 hi/lo
    split_arr<<<(B_ * S_ * D_) / 1024, 256>>>(x,    xh,  xl);
    split_arr<<<(D_ * D_) / 1024,      256>>>(wq_w, wqh, wql);
    split_arr<<<(D_ * HD_) / 1024,     256>>>(wk_w, wkh, wkl);
    split_arr<<<(D_ * HD_) / 1024,     256>>>(wv_w, wvh, wvl);
    split_arr<<<(D_ * D_) / 1024,      256>>>(wo_w, woh, wol);

    // Q = (x @ wq + bq) * scale  -> split bf16
    tc_gemm2<<<dim3(16, 32, 1), blk, SMEM_G2>>>(
        xh, xl, wqh, wql, wq_b, nullptr, qh, ql,
        wqh, wql, wq_b, nullptr, qh, ql, D_, D_, scale);
    // K,V = x @ wk/wv + b  -> split bf16 (z selects)
    tc_gemm2<<<dim3(1, 32, 2), blk, SMEM_G2>>>(
        xh, xl, wkh, wkl, wk_b, nullptr, kh, kl,
        wvh, wvl, wv_b, nullptr, vh, vl, HD_, D_, 1.0f);
    // attention -> split bf16 att
    flash_hmma2<<<dim3(S_ / 128, H_, B_), blk, SMEM_FL2>>>(
        mask, qh, ql, kh, kl, vh, vl, ath, atl);
    // out = att @ wo + bo  (fp32)
    tc_gemm2<<<dim3(16, 32, 1), blk, SMEM_G2>>>(
        ath, atl, woh, wol, wo_b, out, nullptr, nullptr,
        woh, wol, wo_b, out, nullptr, nullptr, D_, D_, 1.0f);
}

// round 10
// speedup vs baseline: 2.9976x; 1.0668x over previous
#include <cuda_runtime.h>
#include <cuda_bf16.h>
#include <cstdint>
#include <math.h>

// Problem constants
constexpr int B_  = 2;
constexpr int S_  = 2048;
constexpr int D_  = 2048;
constexpr int H_  = 16;
constexpr int HD_ = 128;

// ---- pre-split bf16 scratch (device globals; no allocation allowed) ----
__device__ __nv_bfloat16 g_xh [(size_t)B_ * S_ * D_], g_xl [(size_t)B_ * S_ * D_];
__device__ __nv_bfloat16 g_wqh[(size_t)D_ * D_],      g_wql[(size_t)D_ * D_];
__device__ __nv_bfloat16 g_wkh[(size_t)D_ * HD_],     g_wkl[(size_t)D_ * HD_];
__device__ __nv_bfloat16 g_wvh[(size_t)D_ * HD_],     g_wvl[(size_t)D_ * HD_];
__device__ __nv_bfloat16 g_woh[(size_t)D_ * D_],      g_wol[(size_t)D_ * D_];
__device__ __nv_bfloat16 g_qh [(size_t)B_ * S_ * D_], g_ql [(size_t)B_ * S_ * D_];
__device__ __nv_bfloat16 g_kh [(size_t)B_ * S_ * HD_], g_kl [(size_t)B_ * S_ * HD_];
__device__ __nv_bfloat16 g_vh [(size_t)B_ * S_ * HD_], g_vl [(size_t)B_ * S_ * HD_];
__device__ __nv_bfloat16 g_ath[(size_t)B_ * S_ * D_], g_atl[(size_t)B_ * S_ * D_];

// ===========================================================================
// PTX helpers — baseline ISA only (mma.sync sm_80+, ldmatrix, cp.async).
// ===========================================================================
__device__ __forceinline__ uint32_t smem_u32(const void* p) {
    uint32_t a;
    asm("{ .reg .u64 t; cvta.to.shared.u64 t, %1; cvt.u32.u64 %0, t; }"
        : "=r"(a) : "l"(p));
    return a;
}
__device__ __forceinline__ void ldsm_x4(uint32_t* r, uint32_t addr) {
    asm volatile("ldmatrix.sync.aligned.m8n8.x4.shared.b16 {%0,%1,%2,%3}, [%4];"
                 : "=r"(r[0]), "=r"(r[1]), "=r"(r[2]), "=r"(r[3]) : "r"(addr));
}
__device__ __forceinline__ void ldsm_x4_t(uint32_t* r, uint32_t addr) {
    asm volatile("ldmatrix.sync.aligned.m8n8.x4.trans.shared.b16 {%0,%1,%2,%3}, [%4];"
                 : "=r"(r[0]), "=r"(r[1]), "=r"(r[2]), "=r"(r[3]) : "r"(addr));
}
__device__ __forceinline__ void ldsm_x2_t(uint32_t* r, uint32_t addr) {
    asm volatile("ldmatrix.sync.aligned.m8n8.x2.trans.shared.b16 {%0,%1}, [%2];"
                 : "=r"(r[0]), "=r"(r[1]) : "r"(addr));
}
__device__ __forceinline__ void mma16816(float* c, const uint32_t* a, const uint32_t* b) {
    asm volatile(
        "mma.sync.aligned.m16n8k16.row.col.f32.bf16.bf16.f32 "
        "{%0,%1,%2,%3}, {%4,%5,%6,%7}, {%8,%9}, {%0,%1,%2,%3};"
        : "+f"(c[0]), "+f"(c[1]), "+f"(c[2]), "+f"(c[3])
        : "r"(a[0]), "r"(a[1]), "r"(a[2]), "r"(a[3]), "r"(b[0]), "r"(b[1]));
}
__device__ __forceinline__ void cp16(uint32_t dst, const void* src) {
    asm volatile("cp.async.cg.shared.global [%0], [%1], 16;" :: "r"(dst), "l"(src));
}
#define CP_COMMIT() asm volatile("cp.async.commit_group;" ::: "memory")
template<int N> __device__ __forceinline__ void cp_wait() {
    asm volatile("cp.async.wait_group %0;" :: "n"(N) : "memory");
}
__device__ __forceinline__ void l2_prefetch(const void* p) {
    asm volatile("prefetch.global.L2 [%0];" :: "l"(p));
}

__device__ __forceinline__ void split4(float4 v, uint2& hp, uint2& lp) {
    __nv_bfloat16 hx = __float2bfloat16(v.x), hy = __float2bfloat16(v.y);
    __nv_bfloat16 hz = __float2bfloat16(v.z), hw = __float2bfloat16(v.w);
    __nv_bfloat16 lx = __float2bfloat16(v.x - __bfloat162float(hx));
    __nv_bfloat16 ly = __float2bfloat16(v.y - __bfloat162float(hy));
    __nv_bfloat16 lz = __float2bfloat16(v.z - __bfloat162float(hz));
    __nv_bfloat16 lw = __float2bfloat16(v.w - __bfloat162float(hw));
    hp.x = (uint32_t)__bfloat16_as_ushort(hx) | ((uint32_t)__bfloat16_as_ushort(hy) << 16);
    hp.y = (uint32_t)__bfloat16_as_ushort(hz) | ((uint32_t)__bfloat16_as_ushort(hw) << 16);
    lp.x = (uint32_t)__bfloat16_as_ushort(lx) | ((uint32_t)__bfloat16_as_ushort(ly) << 16);
    lp.y = (uint32_t)__bfloat16_as_ushort(lz) | ((uint32_t)__bfloat16_as_ushort(lw) << 16);
}
__device__ __forceinline__ void split2(float x, float y, uint32_t& hi, uint32_t& lo) {
    __nv_bfloat16 hx = __float2bfloat16(x), hy = __float2bfloat16(y);
    __nv_bfloat16 lx = __float2bfloat16(x - __bfloat162float(hx));
    __nv_bfloat16 ly = __float2bfloat16(y - __bfloat162float(hy));
    hi = (uint32_t)__bfloat16_as_ushort(hx) | ((uint32_t)__bfloat16_as_ushort(hy) << 16);
    lo = (uint32_t)__bfloat16_as_ushort(lx) | ((uint32_t)__bfloat16_as_ushort(ly) << 16);
}

// exp2 on the FMA pipe: deg-5 poly, rel err ~2e-6.
__device__ __forceinline__ float exp2p(float y) {
    y = fmaxf(y, -126.0f);
    float k = rintf(y);
    float f = y - k;
    float p = 1.3333558146e-3f;
    p = fmaf(p, f, 9.6181291058e-3f);
    p = fmaf(p, f, 5.5504108664e-2f);
    p = fmaf(p, f, 2.4022650696e-1f);
    p = fmaf(p, f, 6.9314718056e-1f);
    p = fmaf(p, f, 1.0f);
    return p * __int_as_float(((int)k + 127) << 23);
}

// ===========================================================================
// Prepass (single launch): fp32 -> (hi, lo) bf16, all 5 arrays.
// One block = 1024 elems. Regions: x 8192, wq 4096, wk 256, wv 256, wo 4096.
// ===========================================================================
__global__ void split_all(const float* __restrict__ x,  const float* __restrict__ wq,
                          const float* __restrict__ wk, const float* __restrict__ wv,
                          const float* __restrict__ wo)
{
    int bx = blockIdx.x;
    const float* src; __nv_bfloat16 *h, *l; int off;
    if (bx < 8192)       { src = x;  h = g_xh;  l = g_xl;  off = bx; }
    else if (bx < 12288) { src = wq; h = g_wqh; l = g_wql; off = bx - 8192; }
    else if (bx < 12544) { src = wk; h = g_wkh; l = g_wkl; off = bx - 12288; }
    else if (bx < 12800) { src = wv; h = g_wvh; l = g_wvl; off = bx - 12544; }
    else                 { src = wo; h = g_woh; l = g_wol; off = bx - 12800; }
    size_t i = ((size_t)off * 256 + threadIdx.x) * 4;
    float4 v = *(const float4*)(src + i);
    uint2 hp, lp;
    split4(v, hp, lp);
    *(uint2*)(h + i) = hp;
    *(uint2*)(l + i) = lp;
}

// ===========================================================================
// tc_gemm3: bf16-split HMMA GEMM, cp.async 3-stage pipe, region-decoded.
// mode 0: merged QKV projection. grid (18, 32): bx<16 -> Q (prescaled split
//         out), bx==16 -> K, bx==17 -> V. A = g_xh/g_xl.
// mode 1: O-proj. grid (16, 32). A = g_ath/g_atl, B = wo, fp32 out Cf.
// CTA tile 128x128(Q/O) or 128x128-of-128(KV), K chunk 32, 8 warps 2m x 4n.
// D += Ah*Bh + Ah*Bl + Al*Bh (fp32 acc).
// ===========================================================================
constexpr int KC2  = 32;
constexpr int SAe  = 40;
constexpr int SBe  = 136;
constexpr int AL_E = 128 * SAe;            // 5120
constexpr int BH_E = 2 * 128 * SAe;        // 10240
constexpr int BL_E = BH_E + KC2 * SBe;     // 14592
constexpr int STG_E = BL_E + KC2 * SBe;    // 18944 elems/stage
constexpr int SMEM_G2 = 3 * STG_E * 2;     // 113664 B

__global__ __launch_bounds__(256)
void tc_gemm3(int mode, const float* __restrict__ biasQ, const float* __restrict__ biasK,
              const float* __restrict__ biasV, float* __restrict__ CfOut)
{
    const int bx = blockIdx.x;
    const __nv_bfloat16 *Agh, *Agl, *Bgh, *Bgl;
    const float* bia;
    __nv_bfloat16 *Ch = nullptr, *Cl = nullptr;
    float* Cf = nullptr;
    int NW, colL;
    float osc = 1.0f;
    if (mode == 0) {
        Agh = g_xh; Agl = g_xl;
        if (bx < 16) {
            Bgh = g_wqh; Bgl = g_wql; bia = biasQ; NW = D_;  colL = bx * 128;
            Ch = g_qh; Cl = g_ql; osc = 0.08838834764831845f;   // 1/sqrt(128)
        } else if (bx == 16) {
            Bgh = g_wkh; Bgl = g_wkl; bia = biasK; NW = HD_; colL = 0;
            Ch = g_kh; Cl = g_kl;
        } else {
            Bgh = g_wvh; Bgl = g_wvl; bia = biasV; NW = HD_; colL = 0;
            Ch = g_vh; Cl = g_vl;
        }
    } else {
        Agh = g_ath; Agl = g_atl;
        Bgh = g_woh; Bgl = g_wol; bia = biasQ; NW = D_; colL = bx * 128;
        Cf = CfOut;
    }
    const int K = D_;

    extern __shared__ unsigned short smu[];
    const uint32_t sb = smem_u32(smu);
    const int tid  = threadIdx.x;
    const int wid  = tid >> 5;
    const int lane = tid & 31;
    const int row0 = blockIdx.y * 128;

    const int wm = wid >> 2;
    const int wn = wid & 3;
    const int la = lane & 15;
    const int lb = lane >> 4;

    uint32_t offA[4], offB[4];
#pragma unroll
    for (int mi = 0; mi < 4; ++mi)
        offA[mi] = (uint32_t)(((wm * 64 + mi * 16 + la) * SAe + lb * 8) * 2);
#pragma unroll
    for (int ni = 0; ni < 4; ++ni)
        offB[ni] = (uint32_t)((la * SBe + wn * 32 + ni * 8) * 2);

    auto issue = [&](int c, int stg) {
        const int kc = c * KC2;
        const uint32_t sbase = sb + (uint32_t)(stg * STG_E) * 2;
#pragma unroll
        for (int u = 0; u < 2; ++u) {
            int ci2 = u * 256 + tid;
            int r = ci2 >> 2, p = ci2 & 3;
            uint32_t doff = (uint32_t)((r * SAe + p * 8) * 2);
            const size_t gsrc = (size_t)(row0 + r) * K + kc + p * 8;
            cp16(sbase + doff, Agh + gsrc);
            cp16(sbase + AL_E * 2 + doff, Agl + gsrc);
        }
#pragma unroll
        for (int u = 0; u < 2; ++u) {
            int ci2 = u * 256 + tid;
            int k = ci2 >> 4, p = ci2 & 15;
            uint32_t doff = (uint32_t)((k * SBe + p * 8) * 2);
            const size_t gsrc = (size_t)(kc + k) * NW + colL + p * 8;
            cp16(sbase + BH_E * 2 + doff, Bgh + gsrc);
            cp16(sbase + BL_E * 2 + doff, Bgl + gsrc);
        }
    };

    float acc[4][4][4];
#pragma unroll
    for (int mi = 0; mi < 4; ++mi)
#pragma unroll
        for (int ni = 0; ni < 4; ++ni)
#pragma unroll
            for (int r = 0; r < 4; ++r) acc[mi][ni][r] = 0.0f;

    issue(0, 0); CP_COMMIT();
    issue(1, 1); CP_COMMIT();

    const int NCH = K / KC2;
    for (int ci = 0; ci < NCH; ++ci) {
        cp_wait<1>();
        __syncthreads();
        if (ci + 2 < NCH) { issue(ci + 2, (ci + 2) % 3); CP_COMMIT(); }

        const uint32_t bAh = sb + (uint32_t)((ci % 3) * STG_E) * 2;
        const uint32_t bAl = bAh + AL_E * 2;
        const uint32_t bBh = sb + (uint32_t)((ci % 3) * STG_E + BH_E) * 2;
        const uint32_t bBl = bBh + (BL_E - BH_E) * 2;

#pragma unroll
        for (int kk = 0; kk < 2; ++kk) {
            const uint32_t dA = (uint32_t)(kk * 16 * 2);
            const uint32_t dB = (uint32_t)(kk * 16 * SBe * 2);
            uint32_t ah[4][4], al[4][4], bh[4][2], bl[4][2];
#pragma unroll
            for (int mi = 0; mi < 4; ++mi) {
                ldsm_x4(ah[mi], bAh + offA[mi] + dA);
                ldsm_x4(al[mi], bAl + offA[mi] + dA);
            }
#pragma unroll
            for (int ni = 0; ni < 4; ++ni) {
                ldsm_x2_t(bh[ni], bBh + offB[ni] + dB);
                ldsm_x2_t(bl[ni], bBl + offB[ni] + dB);
            }
#pragma unroll
            for (int mi = 0; mi < 4; ++mi)
#pragma unroll
                for (int ni = 0; ni < 4; ++ni)
                    mma16816(acc[mi][ni], ah[mi], bh[ni]);
#pragma unroll
            for (int mi = 0; mi < 4; ++mi)
#pragma unroll
                for (int ni = 0; ni < 4; ++ni)
                    mma16816(acc[mi][ni], ah[mi], bl[ni]);
#pragma unroll
            for (int mi = 0; mi < 4; ++mi)
#pragma unroll
                for (int ni = 0; ni < 4; ++ni)
                    mma16816(acc[mi][ni], al[mi], bh[ni]);
        }
    }

    // ---- epilogue ----
    const int g = lane >> 2, t = lane & 3;
    if (Cf) {
#pragma unroll
        for (int mi = 0; mi < 4; ++mi)
#pragma unroll
            for (int ni = 0; ni < 4; ++ni) {
                int row = row0 + wm * 64 + mi * 16 + g;
                int col = colL + wn * 32 + ni * 8 + 2 * t;
                float b0v = bia[col], b1v = bia[col + 1];
                *(float2*)&Cf[(size_t)row * NW + col] =
                    make_float2(acc[mi][ni][0] + b0v, acc[mi][ni][1] + b1v);
                *(float2*)&Cf[(size_t)(row + 8) * NW + col] =
                    make_float2(acc[mi][ni][2] + b0v, acc[mi][ni][3] + b1v);
            }
    } else {
#pragma unroll
        for (int mi = 0; mi < 4; ++mi)
#pragma unroll
            for (int ni = 0; ni < 4; ++ni) {
                int row = row0 + wm * 64 + mi * 16 + g;
                int col = colL + wn * 32 + ni * 8 + 2 * t;
                float b0v = bia[col], b1v = bia[col + 1];
                uint32_t hi, lo;
                split2((acc[mi][ni][0] + b0v) * osc, (acc[mi][ni][1] + b1v) * osc, hi, lo);
                *(uint32_t*)(Ch + (size_t)row * NW + col) = hi;
                *(uint32_t*)(Cl + (size_t)row * NW + col) = lo;
                split2((acc[mi][ni][2] + b0v) * osc, (acc[mi][ni][3] + b1v) * osc, hi, lo);
                *(uint32_t*)(Ch + (size_t)(row + 8) * NW + col) = hi;
                *(uint32_t*)(Cl + (size_t)(row + 8) * NW + col) = lo;
            }
    }
}

// ===========================================================================
// flash_hmma3: pre-split bf16 Q/K/V (device globals) via cp.async; split
// bf16 att output. CTA: 128 q-rows x (head, batch); 8 warps x 16 q-rows;
// KV tile Bc=64, 2-stage pipeline, one barrier/tile; next-tile mask rows
// prefetched into L2 during the MMA phase.
// ===========================================================================
constexpr int FSe   = 136;
constexpr int QL_E  = 128 * FSe;
constexpr int ST0_E = 2 * 128 * FSe;
constexpr int KST_E = 4 * 64 * FSe;
constexpr int KL_S  = 64 * FSe;
constexpr int VH_S  = 2 * 64 * FSe;
constexpr int VL_S  = 3 * 64 * FSe;
constexpr int SMEM_FL2 = (ST0_E + 2 * KST_E) * 2;   // 208896 B

__global__ __launch_bounds__(256)
void flash_hmma3(const float* __restrict__ mask)
{
    extern __shared__ unsigned short smu[];
    const uint32_t sb = smem_u32(smu);
    const int tid  = threadIdx.x;
    const int wid  = tid >> 5;
    const int lane = tid & 31;
    const int q0 = blockIdx.x * 128;
    const int h  = blockIdx.y;
    const int b  = blockIdx.z;
    const int qr = wid * 16;
    const int g  = lane >> 2;
    const int t  = lane & 3;
    const int la = lane & 15;
    const int lb = lane >> 4;
    const float L2E = 1.4426950408889634f;

    // ---- Q tile (pre-split, pre-scaled) via cp.async ----
#pragma unroll
    for (int u = 0; u < 8; ++u) {
        int ci2 = u * 256 + tid;
        int r = ci2 >> 4, p = ci2 & 15;
        const size_t gsrc = ((size_t)(b * S_ + q0 + r)) * D_ + h * HD_ + p * 8;
        uint32_t doff = (uint32_t)((r * FSe + p * 8) * 2);
        cp16(sb + doff, g_qh + gsrc);
        cp16(sb + QL_E * 2 + doff, g_ql + gsrc);
    }
    CP_COMMIT();

    auto issueKV = [&](int c, int stg) {
        const int kv0 = c * 64;
        const uint32_t sbase = sb + (uint32_t)(ST0_E + stg * KST_E) * 2;
#pragma unroll
        for (int u = 0; u < 4; ++u) {
            int ci2 = u * 256 + tid;
            int r = ci2 >> 4, p = ci2 & 15;
            const size_t gsrc = ((size_t)(b * S_ + kv0 + r)) * HD_ + p * 8;
            uint32_t doff = (uint32_t)((r * FSe + p * 8) * 2);
            cp16(sbase + doff, g_kh + gsrc);
            cp16(sbase + KL_S * 2 + doff, g_kl + gsrc);
            cp16(sbase + VH_S * 2 + doff, g_vh + gsrc);
            cp16(sbase + VL_S * 2 + doff, g_vl + gsrc);
        }
    };

    issueKV(0, 0); CP_COMMIT();
    cp_wait<1>();
    __syncthreads();

    // ---- Q A-frags to registers (persist) ----
    uint32_t ah[8][4], al[8][4];
#pragma unroll
    for (int ks = 0; ks < 8; ++ks) {
        uint32_t ad = sb + (uint32_t)(((qr + la) * FSe + ks * 16 + lb * 8) * 2);
        ldsm_x4(ah[ks], ad);
        ldsm_x4(al[ks], ad + QL_E * 2);
    }

    float m0 = -1e30f, m1 = -1e30f, l0 = 0.0f, l1 = 0.0f;
    float o[16][4];
#pragma unroll
    for (int nf = 0; nf < 16; ++nf)
#pragma unroll
        for (int r = 0; r < 4; ++r) o[nf][r] = 0.0f;

    constexpr int NT = S_ / 64;
    for (int ci = 0; ci < NT; ++ci) {
        cp_wait<0>();
        __syncthreads();
        if (ci + 1 < NT) { issueKV(ci + 1, (ci + 1) & 1); CP_COMMIT(); }

        const int kv0 = ci * 64;
        const uint32_t sK = sb + (uint32_t)(ST0_E + (ci & 1) * KST_E) * 2;

        const float* mp0 = mask + ((size_t)b * S_ + (q0 + qr + g)) * S_ + kv0 + 2 * t;
        const float* mp1 = mp0 + 8 * (size_t)S_;
        if (ci + 1 < NT) {          // warm L2 for next tile's mask rows
            l2_prefetch(mp0 + 64); l2_prefetch(mp0 + 96);
            l2_prefetch(mp1 + 64); l2_prefetch(mp1 + 96);
        }

        // ---- S = Q @ K^T (hh + lh + hl) ----
        float s[8][4];
#pragma unroll
        for (int j = 0; j < 8; ++j)
#pragma unroll
            for (int r = 0; r < 4; ++r) s[j][r] = 0.0f;

#pragma unroll
        for (int ks = 0; ks < 8; ++ks) {
            uint32_t t4[4], khf[8][2];
#pragma unroll
            for (int gg = 0; gg < 4; ++gg) {
                uint32_t ad = sK + (uint32_t)(((gg * 16 + la) * FSe + ks * 16 + lb * 8) * 2);
                ldsm_x4(t4, ad);
                khf[2 * gg][0] = t4[0]; khf[2 * gg][1] = t4[2];
                khf[2 * gg + 1][0] = t4[1]; khf[2 * gg + 1][1] = t4[3];
            }
#pragma unroll
            for (int j = 0; j < 8; ++j) mma16816(s[j], ah[ks], khf[j]);
#pragma unroll
            for (int j = 0; j < 8; ++j) mma16816(s[j], al[ks], khf[j]);
            uint32_t klf[8][2];
#pragma unroll
            for (int gg = 0; gg < 4; ++gg) {
                uint32_t ad = sK + (uint32_t)((KL_S + (gg * 16 + la) * FSe + ks * 16 + lb * 8) * 2);
                ldsm_x4(t4, ad);
                klf[2 * gg][0] = t4[0]; klf[2 * gg][1] = t4[2];
                klf[2 * gg + 1][0] = t4[1]; klf[2 * gg + 1][1] = t4[3];
            }
#pragma unroll
            for (int j = 0; j < 8; ++j) mma16816(s[j], ah[ks], klf[j]);
        }

        // ---- + mask ----
#pragma unroll
        for (int j = 0; j < 8; ++j) {
            float2 u0 = *(const float2*)(mp0 + j * 8);
            float2 u1 = *(const float2*)(mp1 + j * 8);
            s[j][0] += u0.x; s[j][1] += u0.y;
            s[j][2] += u1.x; s[j][3] += u1.y;
        }

        // ---- online softmax ----
        float mx0 = -1e30f, mx1 = -1e30f;
#pragma unroll
        for (int j = 0; j < 8; ++j) {
            mx0 = fmaxf(mx0, fmaxf(s[j][0], s[j][1]));
            mx1 = fmaxf(mx1, fmaxf(s[j][2], s[j][3]));
        }
        mx0 = fmaxf(mx0, __shfl_xor_sync(0xffffffffu, mx0, 1));
        mx0 = fmaxf(mx0, __shfl_xor_sync(0xffffffffu, mx0, 2));
        mx1 = fmaxf(mx1, __shfl_xor_sync(0xffffffffu, mx1, 1));
        mx1 = fmaxf(mx1, __shfl_xor_sync(0xffffffffu, mx1, 2));
        float nm0 = fmaxf(m0, mx0), nm1 = fmaxf(m1, mx1);
        float a0 = exp2p((m0 - nm0) * L2E);
        float a1 = exp2p((m1 - nm1) * L2E);
        m0 = nm0; m1 = nm1;
        float b0 = nm0 * L2E, b1 = nm1 * L2E;
        float nl0 = 0.0f, nl1 = 0.0f;
#pragma unroll
        for (int j = 0; j < 8; ++j) {
            s[j][0] = exp2p(fmaf(s[j][0], L2E, -b0));
            s[j][1] = exp2p(fmaf(s[j][1], L2E, -b0));
            s[j][2] = exp2p(fmaf(s[j][2], L2E, -b1));
            s[j][3] = exp2p(fmaf(s[j][3], L2E, -b1));
            nl0 += s[j][0] + s[j][1];
            nl1 += s[j][2] + s[j][3];
        }
        nl0 += __shfl_xor_sync(0xffffffffu, nl0, 1);
        nl0 += __shfl_xor_sync(0xffffffffu, nl0, 2);
        nl1 += __shfl_xor_sync(0xffffffffu, nl1, 1);
        nl1 += __shfl_xor_sync(0xffffffffu, nl1, 2);
        l0 = l0 * a0 + nl0;
        l1 = l1 * a1 + nl1;

        // ---- P -> split A-frags ----
        uint32_t ph[4][4], pl[4][4];
#pragma unroll
        for (int k2 = 0; k2 < 4; ++k2) {
            split2(s[2 * k2][0],     s[2 * k2][1],     ph[k2][0], pl[k2][0]);
            split2(s[2 * k2][2],     s[2 * k2][3],     ph[k2][1], pl[k2][1]);
            split2(s[2 * k2 + 1][0], s[2 * k2 + 1][1], ph[k2][2], pl[k2][2]);
            split2(s[2 * k2 + 1][2], s[2 * k2 + 1][3], ph[k2][3], pl[k2][3]);
        }

        // ---- rescale O ----
#pragma unroll
        for (int nf = 0; nf < 16; ++nf) {
            o[nf][0] *= a0; o[nf][1] *= a0;
            o[nf][2] *= a1; o[nf][3] *= a1;
        }

        // ---- O += P @ V (ph*vh + pl*vh + ph*vl) ----
#pragma unroll
        for (int k2 = 0; k2 < 4; ++k2) {
#pragma unroll
            for (int half = 0; half < 2; ++half) {
                uint32_t t4[4], vhf[8][2];
#pragma unroll
                for (int gi = 0; gi < 4; ++gi) {
                    int n0 = (half * 4 + gi) * 16;
                    uint32_t ad = sK + (uint32_t)((VH_S + (k2 * 16 + la) * FSe + n0 + lb * 8) * 2);
                    ldsm_x4_t(t4, ad);
                    vhf[2 * gi][0] = t4[0]; vhf[2 * gi][1] = t4[1];
                    vhf[2 * gi + 1][0] = t4[2]; vhf[2 * gi + 1][1] = t4[3];
                }
#pragma unroll
                for (int f = 0; f < 8; ++f) mma16816(o[half * 8 + f], ph[k2], vhf[f]);
#pragma unroll
                for (int f = 0; f < 8; ++f) mma16816(o[half * 8 + f], pl[k2], vhf[f]);
                uint32_t vlf[8][2];
#pragma unroll
                for (int gi = 0; gi < 4; ++gi) {
                    int n0 = (half * 4 + gi) * 16;
                    uint32_t ad = sK + (uint32_t)((VL_S + (k2 * 16 + la) * FSe + n0 + lb * 8) * 2);
                    ldsm_x4_t(t4, ad);
                    vlf[2 * gi][0] = t4[0]; vlf[2 * gi][1] = t4[1];
                    vlf[2 * gi + 1][0] = t4[2]; vlf[2 * gi + 1][1] = t4[3];
                }
#pragma unroll
                for (int f = 0; f < 8; ++f) mma16816(o[half * 8 + f], ph[k2], vlf[f]);
            }
        }
    }

    // ---- finalize: O / l -> split bf16 att ----
    float il0 = 1.0f / l0, il1 = 1.0f / l1;
    size_t base0 = ((size_t)(b * S_ + q0 + qr + g)) * D_ + h * HD_ + 2 * t;
    size_t base1 = base0 + 8 * (size_t)D_;
#pragma unroll
    for (int nf = 0; nf < 16; ++nf) {
        uint32_t hi, lo;
        split2(o[nf][0] * il0, o[nf][1] * il0, hi, lo);
        *(uint32_t*)(g_ath + base0 + nf * 8) = hi;
        *(uint32_t*)(g_atl + base0 + nf * 8) = lo;
        split2(o[nf][2] * il1, o[nf][3] * il1, hi, lo);
        *(uint32_t*)(g_ath + base1 + nf * 8) = hi;
        *(uint32_t*)(g_atl + base1 + nf * 8) = lo;
    }
}

// ---------------------------------------------------------------------------
extern "C" void kernel_launch(void* const* d_in, const int* in_sizes, int n_in,
                              void* d_out, int out_size)
{
    (void)in_sizes; (void)n_in; (void)out_size;
    const float* x    = (const float*)d_in[0];
    const float* mask = (const float*)d_in[1];
    const float* wq_w = (const float*)d_in[2];
    const float* wq_b = (const float*)d_in[3];
    const float* wk_w = (const float*)d_in[4];
    const float* wk_b = (const float*)d_in[5];
    const float* wv_w = (const float*)d_in[6];
    const float* wv_b = (const float*)d_in[7];
    const float* wo_w = (const float*)d_in[8];
    const float* wo_b = (const float*)d_in[9];
    float* out = (float*)d_out;

    cudaFuncSetAttribute(tc_gemm3,    cudaFuncAttributeMaxDynamicSharedMemorySize, SMEM_G2);
    cudaFuncSetAttribute(flash_hmma3, cudaFuncAttributeMaxDynamicSharedMemorySize, SMEM_FL2);

    dim3 blk(256);
    // prepass: split all fp32 inputs -> bf16 hi/lo (one launch)
    split_all<<<16896, 256>>>(x, wq_w, wk_w, wv_w, wo_w);
    // merged projection: Q (prescaled split), K, V in one launch
    tc_gemm3<<<dim3(18, 32, 1), blk, SMEM_G2>>>(0, wq_b, wk_b, wv_b, nullptr);
    // attention -> split bf16 att
    flash_hmma3<<<dim3(S_ / 128, H_, B_), blk, SMEM_FL2>>>(mask);
    // out = att @ wo + bo (fp32)
    tc_gemm3<<<dim3(16, 32, 1), blk, SMEM_G2>>>(1, wo_b, nullptr, nullptr, out);
}